// round 1
// baseline (speedup 1.0000x reference)
#include <cuda_runtime.h>
#include <cstddef>

// Problem constants
#define B_   4
#define T_   2048
#define C_   1024
#define H_   16
#define D_   64
#define MTOK (B_ * T_)          // 8192 tokens

// ---------------------------------------------------------------------------
// Scratch (no cudaMalloc allowed): static device globals
// ---------------------------------------------------------------------------
__device__ float g_qkv[(size_t)MTOK * 3 * C_];   // [8192, 3072]
__device__ float g_attn[(size_t)MTOK * C_];      // [8192, 1024]
__device__ float g_conv[(size_t)MTOK * C_];      // [8192, 1024]

// ---------------------------------------------------------------------------
// SGEMM (NT): C[M,N] = A[M,K] @ B[N,K]^T   (both operands K-contiguous)
// 128x128 block tile, BK=16, 256 threads, 8x8 register micro-tile.
// ---------------------------------------------------------------------------
__global__ void __launch_bounds__(256)
sgemm_nt(const float* __restrict__ A, const float* __restrict__ Bm,
         float* __restrict__ Cm, int M, int N, int K)
{
    __shared__ float As[16][128];
    __shared__ float Bs[16][128];

    const int tid  = threadIdx.x;
    const int bm   = blockIdx.y * 128;
    const int bn   = blockIdx.x * 128;
    const int lrow = tid >> 2;          // 0..63
    const int lcol = (tid & 3) << 2;    // 0,4,8,12
    const int tx   = tid & 15;
    const int ty   = tid >> 4;

    float acc[8][8];
#pragma unroll
    for (int i = 0; i < 8; i++)
#pragma unroll
        for (int j = 0; j < 8; j++) acc[i][j] = 0.f;

    for (int k0 = 0; k0 < K; k0 += 16) {
#pragma unroll
        for (int r = 0; r < 2; r++) {
            const int row = lrow + r * 64;
            float4 a = *(const float4*)(A + (size_t)(bm + row) * K + k0 + lcol);
            As[lcol + 0][row] = a.x;
            As[lcol + 1][row] = a.y;
            As[lcol + 2][row] = a.z;
            As[lcol + 3][row] = a.w;
            float4 b = *(const float4*)(Bm + (size_t)(bn + row) * K + k0 + lcol);
            Bs[lcol + 0][row] = b.x;
            Bs[lcol + 1][row] = b.y;
            Bs[lcol + 2][row] = b.z;
            Bs[lcol + 3][row] = b.w;
        }
        __syncthreads();

#pragma unroll
        for (int kk = 0; kk < 16; kk++) {
            float af[8], bf[8];
            *(float4*)(af + 0) = *(const float4*)&As[kk][ty * 8 + 0];
            *(float4*)(af + 4) = *(const float4*)&As[kk][ty * 8 + 4];
            *(float4*)(bf + 0) = *(const float4*)&Bs[kk][tx * 8 + 0];
            *(float4*)(bf + 4) = *(const float4*)&Bs[kk][tx * 8 + 4];
#pragma unroll
            for (int i = 0; i < 8; i++)
#pragma unroll
                for (int j = 0; j < 8; j++)
                    acc[i][j] += af[i] * bf[j];
        }
        __syncthreads();
    }

#pragma unroll
    for (int i = 0; i < 8; i++) {
        float* crow = Cm + (size_t)(bm + ty * 8 + i) * N + bn + tx * 8;
        *(float4*)(crow + 0) = make_float4(acc[i][0], acc[i][1], acc[i][2], acc[i][3]);
        *(float4*)(crow + 4) = make_float4(acc[i][4], acc[i][5], acc[i][6], acc[i][7]);
    }
}

// ---------------------------------------------------------------------------
// Flash attention (causal), fp32.
// Grid: (T/128, B*H). 128 threads, each owns one query row.
// Tiles of 32 keys. Q cached transposed (pad 132), K cached transposed
// (pad 36, float4-aligned rows), V cached row-major — all inner-loop
// shared reads are conflict-free / broadcast.
// ---------------------------------------------------------------------------
#define FBM 128
#define FBN 32
#define QS_LD 132
#define KS_LD 36
#define FLASH_SMEM_FLOATS (64 * QS_LD + 64 * KS_LD + FBN * 64)
#define FLASH_SMEM_BYTES  (FLASH_SMEM_FLOATS * 4)

__global__ void __launch_bounds__(128)
flash_attn(const float* __restrict__ qkv, float* __restrict__ out)
{
    extern __shared__ float sm[];
    float* Qs  = sm;                    // [64][QS_LD]  Qs[d][m]
    float* KsT = Qs + 64 * QS_LD;       // [64][KS_LD]  KsT[d][j]
    float* Vs  = KsT + 64 * KS_LD;      // [32][64]     Vs[j][d]

    const int tid = threadIdx.x;
    const int bh  = blockIdx.y;
    const int b   = bh >> 4;
    const int h   = bh & 15;
    const int m0  = blockIdx.x * FBM;

    const float* qb = qkv + (size_t)b * T_ * 3072 + h * 64;
    const float* kb = qb + 1024;
    const float* vb = qb + 2048;

    // Load Q tile (pre-scaled by 1/sqrt(D)=0.125), transposed.
#pragma unroll 4
    for (int i = 0; i < 64; i++) {
        int flat = i * 128 + tid;
        int m = flat >> 6, d = flat & 63;
        Qs[d * QS_LD + m] = qb[(size_t)(m0 + m) * 3072 + d] * 0.125f;
    }

    float acc[64];
#pragma unroll
    for (int d = 0; d < 64; d++) acc[d] = 0.f;
    float mval = -1e30f, lval = 0.f;
    const int qi = m0 + tid;
    const int ntiles = (m0 + FBM) / FBN;

    for (int kt = 0; kt < ntiles; kt++) {
        const int j0 = kt * FBN;
        __syncthreads();
#pragma unroll
        for (int i = 0; i < 16; i++) {
            int flat = i * 128 + tid;
            int j = flat >> 6, d = flat & 63;
            KsT[d * KS_LD + j] = kb[(size_t)(j0 + j) * 3072 + d];
            Vs[flat]           = vb[(size_t)(j0 + j) * 3072 + d];
        }
        __syncthreads();

        if (qi >= j0) {   // skip fully-masked tiles for this query
            float s[FBN];
#pragma unroll
            for (int j = 0; j < FBN; j++) s[j] = 0.f;

#pragma unroll 4
            for (int d = 0; d < 64; d++) {
                float qd = Qs[d * QS_LD + tid];
                const float4* kr = (const float4*)(KsT + d * KS_LD);
#pragma unroll
                for (int j4 = 0; j4 < 8; j4++) {
                    float4 kv = kr[j4];
                    s[j4 * 4 + 0] += qd * kv.x;
                    s[j4 * 4 + 1] += qd * kv.y;
                    s[j4 * 4 + 2] += qd * kv.z;
                    s[j4 * 4 + 3] += qd * kv.w;
                }
            }

            // causal mask inside the diagonal tile
            const int lim = qi - j0;
#pragma unroll
            for (int j = 0; j < FBN; j++)
                if (j > lim) s[j] = -1e30f;

            float tmax = mval;
#pragma unroll
            for (int j = 0; j < FBN; j++) tmax = fmaxf(tmax, s[j]);

            const float corr = __expf(mval - tmax);
            mval = tmax;
            lval *= corr;
#pragma unroll
            for (int d = 0; d < 64; d++) acc[d] *= corr;

            float psum = 0.f;
#pragma unroll
            for (int j = 0; j < FBN; j++) {
                float p = __expf(s[j] - tmax);
                psum += p;
                s[j] = p;
            }
            lval += psum;

#pragma unroll
            for (int j = 0; j < FBN; j++) {
                const float p = s[j];
                const float4* vr = (const float4*)(Vs + j * 64);
#pragma unroll
                for (int d4 = 0; d4 < 16; d4++) {
                    float4 v = vr[d4];
                    acc[d4 * 4 + 0] += p * v.x;
                    acc[d4 * 4 + 1] += p * v.y;
                    acc[d4 * 4 + 2] += p * v.z;
                    acc[d4 * 4 + 3] += p * v.w;
                }
            }
        }
    }

    const float inv = 1.0f / lval;
    float* orow = out + (size_t)(b * T_ + qi) * C_ + h * 64;
#pragma unroll
    for (int d4 = 0; d4 < 16; d4++) {
        *(float4*)(orow + d4 * 4) = make_float4(acc[d4 * 4 + 0] * inv,
                                                acc[d4 * 4 + 1] * inv,
                                                acc[d4 * 4 + 2] * inv,
                                                acc[d4 * 4 + 3] * inv);
    }
}

// ---------------------------------------------------------------------------
// Depthwise causal conv (K=4) + bias + residual:
// y[b,t,c] = x[b,t,c] + bias[c] + sum_{k=0..3} w[c,k] * x[b, t+k-3, c]
// ---------------------------------------------------------------------------
__global__ void __launch_bounds__(256)
conv_residual(const float* __restrict__ x, const float* __restrict__ w,
              const float* __restrict__ bias, float* __restrict__ y)
{
    int idx = blockIdx.x * blockDim.x + threadIdx.x;
    if (idx >= MTOK * C_) return;
    const int c = idx & (C_ - 1);
    const int t = (idx >> 10) & (T_ - 1);

    float s = bias[c] + x[idx];
#pragma unroll
    for (int k = 0; k < 4; k++) {
        int ts = t + k - 3;
        if (ts >= 0) s += w[c * 4 + k] * x[idx + (k - 3) * C_];
    }
    y[idx] = s;
}

// ---------------------------------------------------------------------------
// Launch
// ---------------------------------------------------------------------------
extern "C" void kernel_launch(void* const* d_in, const int* in_sizes, int n_in,
                              void* d_out, int out_size)
{
    const float* x     = (const float*)d_in[0];
    const float* Wqkv  = (const float*)d_in[1];
    const float* Wout  = (const float*)d_in[2];
    const float* convw = (const float*)d_in[3];
    const float* convb = (const float*)d_in[4];
    float* out = (float*)d_out;

    float *qkv, *attn, *conv;
    cudaGetSymbolAddress((void**)&qkv,  g_qkv);
    cudaGetSymbolAddress((void**)&attn, g_attn);
    cudaGetSymbolAddress((void**)&conv, g_conv);

    // 1) QKV projection: [8192,1024] @ [3072,1024]^T -> [8192,3072]
    sgemm_nt<<<dim3(3072 / 128, MTOK / 128), 256>>>(x, Wqkv, qkv, MTOK, 3072, 1024);

    // 2) Causal flash attention
    cudaFuncSetAttribute(flash_attn, cudaFuncAttributeMaxDynamicSharedMemorySize,
                         FLASH_SMEM_BYTES);
    flash_attn<<<dim3(T_ / FBM, B_ * H_), 128, FLASH_SMEM_BYTES>>>(qkv, attn);

    // 3) Depthwise causal conv + residual
    conv_residual<<<(MTOK * C_) / 256, 256>>>(attn, convw, convb, conv);

    // 4) Output projection: [8192,1024] @ [1024,1024]^T -> d_out
    sgemm_nt<<<dim3(1024 / 128, MTOK / 128), 256>>>(conv, Wout, out, MTOK, 1024, 1024);
}

// round 3
// speedup vs baseline: 1.1691x; 1.1691x over previous
#include <cuda_runtime.h>
#include <cstdint>
#include <cstddef>

// Problem constants
#define B_   4
#define T_   2048
#define C_   1024
#define H_   16
#define MTOK 8192

// ---------------------------------------------------------------------------
// Scratch (static device globals; no cudaMalloc allowed)
// ---------------------------------------------------------------------------
__device__ float g_qkv[(size_t)MTOK * 3 * C_];   // [8192, 3072]
__device__ float g_attn[(size_t)MTOK * C_];      // [8192, 1024]
__device__ float g_conv[(size_t)MTOK * C_];      // [8192, 1024]

// ---------------------------------------------------------------------------
// Helpers
// ---------------------------------------------------------------------------
__device__ __forceinline__ float rtf32(float x) {
    uint32_t u;
    asm("cvt.rna.tf32.f32 %0, %1;" : "=r"(u) : "f"(x));
    return __uint_as_float(u);
}
__device__ __forceinline__ void split_tf(float x, uint32_t& h, uint32_t& l) {
    float fh = rtf32(x);
    h = __float_as_uint(fh);
    l = __float_as_uint(rtf32(x - fh));
}
// D += A(tf32 16x8) * B(tf32 8x8), fp32 accum
__device__ __forceinline__ void mma8(float* d, const uint32_t* a, const uint32_t* b) {
    asm volatile(
        "mma.sync.aligned.m16n8k8.row.col.f32.tf32.tf32.f32 "
        "{%0,%1,%2,%3}, {%4,%5,%6,%7}, {%8,%9}, {%0,%1,%2,%3};"
        : "+f"(d[0]), "+f"(d[1]), "+f"(d[2]), "+f"(d[3])
        : "r"(a[0]), "r"(a[1]), "r"(a[2]), "r"(a[3]), "r"(b[0]), "r"(b[1]));
}

// ---------------------------------------------------------------------------
// SGEMM (NT): C[M,N] = A[M,K] @ B[N,K]^T  (Round-1, known good)
// ---------------------------------------------------------------------------
__global__ void __launch_bounds__(256)
sgemm_nt(const float* __restrict__ A, const float* __restrict__ Bm,
         float* __restrict__ Cm, int M, int N, int K)
{
    __shared__ float As[16][128];
    __shared__ float Bs[16][128];

    const int tid  = threadIdx.x;
    const int bm   = blockIdx.y * 128;
    const int bn   = blockIdx.x * 128;
    const int lrow = tid >> 2;
    const int lcol = (tid & 3) << 2;
    const int tx   = tid & 15;
    const int ty   = tid >> 4;

    float acc[8][8];
#pragma unroll
    for (int i = 0; i < 8; i++)
#pragma unroll
        for (int j = 0; j < 8; j++) acc[i][j] = 0.f;

    for (int k0 = 0; k0 < K; k0 += 16) {
#pragma unroll
        for (int r = 0; r < 2; r++) {
            const int row = lrow + r * 64;
            float4 a = *(const float4*)(A + (size_t)(bm + row) * K + k0 + lcol);
            As[lcol + 0][row] = a.x;
            As[lcol + 1][row] = a.y;
            As[lcol + 2][row] = a.z;
            As[lcol + 3][row] = a.w;
            float4 b = *(const float4*)(Bm + (size_t)(bn + row) * K + k0 + lcol);
            Bs[lcol + 0][row] = b.x;
            Bs[lcol + 1][row] = b.y;
            Bs[lcol + 2][row] = b.z;
            Bs[lcol + 3][row] = b.w;
        }
        __syncthreads();

#pragma unroll
        for (int kk = 0; kk < 16; kk++) {
            float af[8], bf[8];
            *(float4*)(af + 0) = *(const float4*)&As[kk][ty * 8 + 0];
            *(float4*)(af + 4) = *(const float4*)&As[kk][ty * 8 + 4];
            *(float4*)(bf + 0) = *(const float4*)&Bs[kk][tx * 8 + 0];
            *(float4*)(bf + 4) = *(const float4*)&Bs[kk][tx * 8 + 4];
#pragma unroll
            for (int i = 0; i < 8; i++)
#pragma unroll
                for (int j = 0; j < 8; j++)
                    acc[i][j] += af[i] * bf[j];
        }
        __syncthreads();
    }

#pragma unroll
    for (int i = 0; i < 8; i++) {
        float* crow = Cm + (size_t)(bm + ty * 8 + i) * N + bn + tx * 8;
        *(float4*)(crow + 0) = make_float4(acc[i][0], acc[i][1], acc[i][2], acc[i][3]);
        *(float4*)(crow + 4) = make_float4(acc[i][4], acc[i][5], acc[i][6], acc[i][7]);
    }
}

// ---------------------------------------------------------------------------
// Flash attention (causal) on tensor cores: mma.sync m16n8k8 tf32, 3-pass
// error compensation (hi*hi + hi*lo + lo*hi) for both Q@K^T and P@V.
//
// Block: 64 queries, 4 warps (16 rows each). KV tiles of 64 keys.
// Smem: Qs/Ps [64][76] (staging Q, then P), Kh/Kl [64][76] (d-cols permuted
// in (c,c+4) pairs -> fragment loads are single LDS.64), VTh/VTl [64 d][76]
// (transposed, key-cols permuted).
// ---------------------------------------------------------------------------
#define ALD 76
#define ASZ (64 * ALD)
#define ATT_SMEM_BYTES (5 * ASZ * 4)   // 97280

__global__ void __launch_bounds__(128, 2)
flash_attn_mma(const float* __restrict__ qkv, float* __restrict__ out)
{
    extern __shared__ float sm[];
    float* Qs  = sm;               // [64][76]  Q staging, then P buffer
    float* Kh  = sm + ASZ;         // [64 key][76]
    float* Kl  = Kh + ASZ;
    float* VTh = Kl + ASZ;         // [64 d][76 key-permuted]
    float* VTl = VTh + ASZ;

    const int tid  = threadIdx.x;
    const int w    = tid >> 5;
    const int lane = tid & 31;
    const int qr   = lane >> 2;    // 0..7 (fragment row group)
    const int qc   = lane & 3;     // 0..3 (fragment col group)
    const int bh   = blockIdx.y;
    const int b    = bh >> 4;
    const int h    = bh & 15;
    const int m0   = blockIdx.x * 64;

    const float* qb = qkv + (size_t)b * T_ * 3072 + h * 64;
    const float* kb = qb + 1024;
    const float* vb = qb + 2048;

    // ---- stage Q (scaled by 1/8, d-cols permuted into (c,c+4) pairs) ----
#pragma unroll
    for (int i = tid; i < 64 * 16; i += 128) {
        const int row = i >> 4, f4 = i & 15;
        float4 v = *(const float4*)(qb + (size_t)(m0 + row) * 3072 + f4 * 4);
        float* dst = Qs + row * ALD + (f4 >> 1) * 8 + (f4 & 1);
        dst[0] = v.x * 0.125f;
        dst[2] = v.y * 0.125f;
        dst[4] = v.z * 0.125f;
        dst[6] = v.w * 0.125f;
    }
    __syncthreads();

    // ---- preload Q fragments (hi/lo) ----
    const int rs = w * 16 + qr;    // smem row of this thread's frag row
    uint32_t qh[8][4], ql[8][4];
#pragma unroll
    for (int kk = 0; kk < 8; kk++) {
        float2 qa = *(const float2*)(Qs + rs * ALD + kk * 8 + 2 * qc);
        float2 qd = *(const float2*)(Qs + (rs + 8) * ALD + kk * 8 + 2 * qc);
        split_tf(qa.x, qh[kk][0], ql[kk][0]);
        split_tf(qd.x, qh[kk][1], ql[kk][1]);
        split_tf(qa.y, qh[kk][2], ql[kk][2]);
        split_tf(qd.y, qh[kk][3], ql[kk][3]);
    }

    float o[8][4];
#pragma unroll
    for (int dn = 0; dn < 8; dn++)
#pragma unroll
        for (int e = 0; e < 4; e++) o[dn][e] = 0.f;
    float m0v = -1e30f, m1v = -1e30f, l0v = 0.f, l1v = 0.f;

    const int row0 = m0 + rs;      // global query rows (row0, row0+8)

    for (int j0 = 0; j0 <= m0; j0 += 64) {
        const bool diag = (j0 == m0);
        __syncthreads();           // prior iter's smem reads complete

        // ---- stage K (hi/lo, permuted d-cols) ----
#pragma unroll
        for (int i = tid; i < 64 * 16; i += 128) {
            const int row = i >> 4, f4 = i & 15;
            float4 v = *(const float4*)(kb + (size_t)(j0 + row) * 3072 + f4 * 4);
            const int off = row * ALD + (f4 >> 1) * 8 + (f4 & 1);
            float hx = rtf32(v.x), hy = rtf32(v.y), hz = rtf32(v.z), hw = rtf32(v.w);
            Kh[off + 0] = hx; Kl[off + 0] = rtf32(v.x - hx);
            Kh[off + 2] = hy; Kl[off + 2] = rtf32(v.y - hy);
            Kh[off + 4] = hz; Kl[off + 4] = rtf32(v.z - hz);
            Kh[off + 6] = hw; Kl[off + 6] = rtf32(v.w - hw);
        }
        // ---- stage V transposed (hi/lo, permuted key-cols) ----
#pragma unroll
        for (int i = tid; i < 64 * 16; i += 128) {
            const int key = i >> 4, f4 = i & 15;
            float4 v = *(const float4*)(vb + (size_t)(j0 + key) * 3072 + f4 * 4);
            const int j = key & 7;
            const int slot = (key >> 3) * 8 + 2 * (j & 3) + (j >> 2);
            const int d0 = f4 * 4;
            float hx = rtf32(v.x), hy = rtf32(v.y), hz = rtf32(v.z), hw = rtf32(v.w);
            VTh[(d0 + 0) * ALD + slot] = hx; VTl[(d0 + 0) * ALD + slot] = rtf32(v.x - hx);
            VTh[(d0 + 1) * ALD + slot] = hy; VTl[(d0 + 1) * ALD + slot] = rtf32(v.y - hy);
            VTh[(d0 + 2) * ALD + slot] = hz; VTl[(d0 + 2) * ALD + slot] = rtf32(v.z - hz);
            VTh[(d0 + 3) * ALD + slot] = hw; VTl[(d0 + 3) * ALD + slot] = rtf32(v.w - hw);
        }
        __syncthreads();

        // ---- S = Q @ K^T (compensated) ----
        float s[8][4];
#pragma unroll
        for (int n = 0; n < 8; n++)
#pragma unroll
            for (int e = 0; e < 4; e++) s[n][e] = 0.f;

#pragma unroll
        for (int kk = 0; kk < 8; kk++) {
#pragma unroll
            for (int n = 0; n < 8; n++) {
                const int koff = (n * 8 + qr) * ALD + kk * 8 + 2 * qc;
                float2 fh = *(const float2*)(Kh + koff);
                float2 fl = *(const float2*)(Kl + koff);
                uint32_t bhf[2] = { __float_as_uint(fh.x), __float_as_uint(fh.y) };
                uint32_t blf[2] = { __float_as_uint(fl.x), __float_as_uint(fl.y) };
                mma8(s[n], qh[kk], bhf);
                mma8(s[n], qh[kk], blf);
                mma8(s[n], ql[kk], bhf);
            }
        }

        // ---- causal mask (diagonal tile only) ----
        if (diag) {
#pragma unroll
            for (int n = 0; n < 8; n++) {
                const int key = j0 + n * 8 + 2 * qc;
                if (key     > row0)     s[n][0] = -1e30f;
                if (key + 1 > row0)     s[n][1] = -1e30f;
                if (key     > row0 + 8) s[n][2] = -1e30f;
                if (key + 1 > row0 + 8) s[n][3] = -1e30f;
            }
        }

        // ---- online softmax ----
        float mx0 = -1e30f, mx1 = -1e30f;
#pragma unroll
        for (int n = 0; n < 8; n++) {
            mx0 = fmaxf(mx0, fmaxf(s[n][0], s[n][1]));
            mx1 = fmaxf(mx1, fmaxf(s[n][2], s[n][3]));
        }
        mx0 = fmaxf(mx0, __shfl_xor_sync(0xffffffffu, mx0, 1));
        mx0 = fmaxf(mx0, __shfl_xor_sync(0xffffffffu, mx0, 2));
        mx1 = fmaxf(mx1, __shfl_xor_sync(0xffffffffu, mx1, 1));
        mx1 = fmaxf(mx1, __shfl_xor_sync(0xffffffffu, mx1, 2));
        const float mn0 = fmaxf(m0v, mx0);
        const float mn1 = fmaxf(m1v, mx1);
        const float c0 = __expf(m0v - mn0);
        const float c1 = __expf(m1v - mn1);
        m0v = mn0; m1v = mn1;
        l0v *= c0;  l1v *= c1;
#pragma unroll
        for (int dn = 0; dn < 8; dn++) {
            o[dn][0] *= c0; o[dn][1] *= c0;
            o[dn][2] *= c1; o[dn][3] *= c1;
        }

        float ps0 = 0.f, ps1 = 0.f;
#pragma unroll
        for (int n = 0; n < 8; n++) {
            float p0 = __expf(s[n][0] - mn0);
            float p1 = __expf(s[n][1] - mn0);
            float p2 = __expf(s[n][2] - mn1);
            float p3 = __expf(s[n][3] - mn1);
            ps0 += p0 + p1;
            ps1 += p2 + p3;
            // store P to Ps (own rows only -> warp-local)
            *(float2*)(Qs + rs * ALD + n * 8 + 2 * qc)       = make_float2(p0, p1);
            *(float2*)(Qs + (rs + 8) * ALD + n * 8 + 2 * qc) = make_float2(p2, p3);
        }
        ps0 += __shfl_xor_sync(0xffffffffu, ps0, 1);
        ps0 += __shfl_xor_sync(0xffffffffu, ps0, 2);
        ps1 += __shfl_xor_sync(0xffffffffu, ps1, 1);
        ps1 += __shfl_xor_sync(0xffffffffu, ps1, 2);
        l0v += ps0; l1v += ps1;
        __syncwarp();

        // ---- O += P @ V (compensated) ----
#pragma unroll
        for (int kk = 0; kk < 8; kk++) {
            uint32_t pah[4], pal[4];
            split_tf(Qs[rs * ALD + kk * 8 + qc],            pah[0], pal[0]);
            split_tf(Qs[(rs + 8) * ALD + kk * 8 + qc],      pah[1], pal[1]);
            split_tf(Qs[rs * ALD + kk * 8 + qc + 4],        pah[2], pal[2]);
            split_tf(Qs[(rs + 8) * ALD + kk * 8 + qc + 4],  pah[3], pal[3]);
#pragma unroll
            for (int dn = 0; dn < 8; dn++) {
                const int voff = (dn * 8 + qr) * ALD + kk * 8 + 2 * qc;
                float2 vh = *(const float2*)(VTh + voff);
                float2 vl = *(const float2*)(VTl + voff);
                uint32_t bvh[2] = { __float_as_uint(vh.x), __float_as_uint(vh.y) };
                uint32_t bvl[2] = { __float_as_uint(vl.x), __float_as_uint(vl.y) };
                mma8(o[dn], pah, bvh);
                mma8(o[dn], pah, bvl);
                mma8(o[dn], pal, bvh);
            }
        }
    }

    // ---- epilogue ----
    const float i0 = 1.f / l0v;
    const float i1 = 1.f / l1v;
    float* o0 = out + ((size_t)b * T_ + row0) * C_ + h * 64;
    float* o1 = o0 + 8 * C_;
#pragma unroll
    for (int dn = 0; dn < 8; dn++) {
        *(float2*)(o0 + dn * 8 + 2 * qc) = make_float2(o[dn][0] * i0, o[dn][1] * i0);
        *(float2*)(o1 + dn * 8 + 2 * qc) = make_float2(o[dn][2] * i1, o[dn][3] * i1);
    }
}

// ---------------------------------------------------------------------------
// Depthwise causal conv (K=4) + bias + residual
// ---------------------------------------------------------------------------
__global__ void __launch_bounds__(256)
conv_residual(const float* __restrict__ x, const float* __restrict__ w,
              const float* __restrict__ bias, float* __restrict__ y)
{
    int idx = blockIdx.x * blockDim.x + threadIdx.x;
    if (idx >= MTOK * C_) return;
    const int c = idx & (C_ - 1);
    const int t = (idx >> 10) & (T_ - 1);

    float s = bias[c] + x[idx];
#pragma unroll
    for (int k = 0; k < 4; k++) {
        int ts = t + k - 3;
        if (ts >= 0) s += w[c * 4 + k] * x[idx + (k - 3) * C_];
    }
    y[idx] = s;
}

// ---------------------------------------------------------------------------
// Launch
// ---------------------------------------------------------------------------
extern "C" void kernel_launch(void* const* d_in, const int* in_sizes, int n_in,
                              void* d_out, int out_size)
{
    const float* x     = (const float*)d_in[0];
    const float* Wqkv  = (const float*)d_in[1];
    const float* Wout  = (const float*)d_in[2];
    const float* convw = (const float*)d_in[3];
    const float* convb = (const float*)d_in[4];
    float* out = (float*)d_out;

    float *qkv, *attn, *conv;
    cudaGetSymbolAddress((void**)&qkv,  g_qkv);
    cudaGetSymbolAddress((void**)&attn, g_attn);
    cudaGetSymbolAddress((void**)&conv, g_conv);

    cudaFuncSetAttribute(flash_attn_mma,
                         cudaFuncAttributeMaxDynamicSharedMemorySize,
                         ATT_SMEM_BYTES);

    // 1) QKV projection: [8192,1024] @ [3072,1024]^T
    sgemm_nt<<<dim3(3072 / 128, MTOK / 128), 256>>>(x, Wqkv, qkv, MTOK, 3072, 1024);

    // 2) Causal flash attention on tensor cores (tf32 compensated)
    flash_attn_mma<<<dim3(T_ / 64, B_ * H_), 128, ATT_SMEM_BYTES>>>(qkv, attn);

    // 3) Depthwise causal conv + residual
    conv_residual<<<(MTOK * C_) / 256, 256>>>(attn, convw, convb, conv);

    // 4) Output projection: [8192,1024] @ [1024,1024]^T
    sgemm_nt<<<dim3(1024 / 128, MTOK / 128), 256>>>(conv, Wout, out, MTOK, 1024, 1024);
}

// round 4
// speedup vs baseline: 1.1705x; 1.0012x over previous
#include <cuda_runtime.h>
#include <cstdint>
#include <cstddef>

// Problem constants
#define B_   4
#define T_   2048
#define C_   1024
#define H_   16
#define MTOK 8192

// ---------------------------------------------------------------------------
// Scratch (static device globals; no cudaMalloc allowed)
// ---------------------------------------------------------------------------
__device__ float g_qkv[(size_t)MTOK * 3 * C_];   // [8192, 3072]
__device__ float g_attn[(size_t)MTOK * C_];      // [8192, 1024]
__device__ float g_conv[(size_t)MTOK * C_];      // [8192, 1024]

// ---------------------------------------------------------------------------
// Helpers
// ---------------------------------------------------------------------------
__device__ __forceinline__ float rtf32(float x) {
    uint32_t u;
    asm("cvt.rna.tf32.f32 %0, %1;" : "=r"(u) : "f"(x));
    return __uint_as_float(u);
}
__device__ __forceinline__ void split_tf(float x, uint32_t& h, uint32_t& l) {
    float fh = rtf32(x);
    h = __float_as_uint(fh);
    l = __float_as_uint(rtf32(x - fh));
}
// D += A(tf32 16x8) * B(tf32 8x8), fp32 accum
__device__ __forceinline__ void mma8(float* d, const uint32_t* a, const uint32_t* b) {
    asm volatile(
        "mma.sync.aligned.m16n8k8.row.col.f32.tf32.tf32.f32 "
        "{%0,%1,%2,%3}, {%4,%5,%6,%7}, {%8,%9}, {%0,%1,%2,%3};"
        : "+f"(d[0]), "+f"(d[1]), "+f"(d[2]), "+f"(d[3])
        : "r"(a[0]), "r"(a[1]), "r"(a[2]), "r"(a[3]), "r"(b[0]), "r"(b[1]));
}

// ---------------------------------------------------------------------------
// SGEMM (NT): C[M,N] = A[M,K] @ B[N,K]^T  (Round-1, known good)
// ---------------------------------------------------------------------------
__global__ void __launch_bounds__(256)
sgemm_nt(const float* __restrict__ A, const float* __restrict__ Bm,
         float* __restrict__ Cm, int M, int N, int K)
{
    __shared__ float As[16][128];
    __shared__ float Bs[16][128];

    const int tid  = threadIdx.x;
    const int bm   = blockIdx.y * 128;
    const int bn   = blockIdx.x * 128;
    const int lrow = tid >> 2;
    const int lcol = (tid & 3) << 2;
    const int tx   = tid & 15;
    const int ty   = tid >> 4;

    float acc[8][8];
#pragma unroll
    for (int i = 0; i < 8; i++)
#pragma unroll
        for (int j = 0; j < 8; j++) acc[i][j] = 0.f;

    for (int k0 = 0; k0 < K; k0 += 16) {
#pragma unroll
        for (int r = 0; r < 2; r++) {
            const int row = lrow + r * 64;
            float4 a = *(const float4*)(A + (size_t)(bm + row) * K + k0 + lcol);
            As[lcol + 0][row] = a.x;
            As[lcol + 1][row] = a.y;
            As[lcol + 2][row] = a.z;
            As[lcol + 3][row] = a.w;
            float4 b = *(const float4*)(Bm + (size_t)(bn + row) * K + k0 + lcol);
            Bs[lcol + 0][row] = b.x;
            Bs[lcol + 1][row] = b.y;
            Bs[lcol + 2][row] = b.z;
            Bs[lcol + 3][row] = b.w;
        }
        __syncthreads();

#pragma unroll
        for (int kk = 0; kk < 16; kk++) {
            float af[8], bf[8];
            *(float4*)(af + 0) = *(const float4*)&As[kk][ty * 8 + 0];
            *(float4*)(af + 4) = *(const float4*)&As[kk][ty * 8 + 4];
            *(float4*)(bf + 0) = *(const float4*)&Bs[kk][tx * 8 + 0];
            *(float4*)(bf + 4) = *(const float4*)&Bs[kk][tx * 8 + 4];
#pragma unroll
            for (int i = 0; i < 8; i++)
#pragma unroll
                for (int j = 0; j < 8; j++)
                    acc[i][j] += af[i] * bf[j];
        }
        __syncthreads();
    }

#pragma unroll
    for (int i = 0; i < 8; i++) {
        float* crow = Cm + (size_t)(bm + ty * 8 + i) * N + bn + tx * 8;
        *(float4*)(crow + 0) = make_float4(acc[i][0], acc[i][1], acc[i][2], acc[i][3]);
        *(float4*)(crow + 4) = make_float4(acc[i][4], acc[i][5], acc[i][6], acc[i][7]);
    }
}

// ---------------------------------------------------------------------------
// Flash attention (causal) on tensor cores: mma.sync m16n8k8 tf32, 3-pass
// error compensation (hi*hi + hi*lo + lo*hi) for both Q@K^T and P@V.
//
// Block: 64 queries, 4 warps (16 rows each). KV tiles of 64 keys.
// Smem: Qs/Ps [64][76] (staging Q, then P), Kh/Kl [64][76] (d-cols permuted
// in (c,c+4) pairs -> fragment loads are single LDS.64), VTh/VTl [64 d][76]
// (transposed, key-cols permuted).
// ---------------------------------------------------------------------------
#define ALD 76
#define ASZ (64 * ALD)
#define ATT_SMEM_BYTES (5 * ASZ * 4)   // 97280

__global__ void __launch_bounds__(128, 2)
flash_attn_mma(const float* __restrict__ qkv, float* __restrict__ out)
{
    extern __shared__ float sm[];
    float* Qs  = sm;               // [64][76]  Q staging, then P buffer
    float* Kh  = sm + ASZ;         // [64 key][76]
    float* Kl  = Kh + ASZ;
    float* VTh = Kl + ASZ;         // [64 d][76 key-permuted]
    float* VTl = VTh + ASZ;

    const int tid  = threadIdx.x;
    const int w    = tid >> 5;
    const int lane = tid & 31;
    const int qr   = lane >> 2;    // 0..7 (fragment row group)
    const int qc   = lane & 3;     // 0..3 (fragment col group)
    const int bh   = blockIdx.y;
    const int b    = bh >> 4;
    const int h    = bh & 15;
    const int m0   = blockIdx.x * 64;

    const float* qb = qkv + (size_t)b * T_ * 3072 + h * 64;
    const float* kb = qb + 1024;
    const float* vb = qb + 2048;

    // ---- stage Q (scaled by 1/8, d-cols permuted into (c,c+4) pairs) ----
#pragma unroll
    for (int i = tid; i < 64 * 16; i += 128) {
        const int row = i >> 4, f4 = i & 15;
        float4 v = *(const float4*)(qb + (size_t)(m0 + row) * 3072 + f4 * 4);
        float* dst = Qs + row * ALD + (f4 >> 1) * 8 + (f4 & 1);
        dst[0] = v.x * 0.125f;
        dst[2] = v.y * 0.125f;
        dst[4] = v.z * 0.125f;
        dst[6] = v.w * 0.125f;
    }
    __syncthreads();

    // ---- preload Q fragments (hi/lo) ----
    const int rs = w * 16 + qr;    // smem row of this thread's frag row
    uint32_t qh[8][4], ql[8][4];
#pragma unroll
    for (int kk = 0; kk < 8; kk++) {
        float2 qa = *(const float2*)(Qs + rs * ALD + kk * 8 + 2 * qc);
        float2 qd = *(const float2*)(Qs + (rs + 8) * ALD + kk * 8 + 2 * qc);
        split_tf(qa.x, qh[kk][0], ql[kk][0]);
        split_tf(qd.x, qh[kk][1], ql[kk][1]);
        split_tf(qa.y, qh[kk][2], ql[kk][2]);
        split_tf(qd.y, qh[kk][3], ql[kk][3]);
    }

    float o[8][4];
#pragma unroll
    for (int dn = 0; dn < 8; dn++)
#pragma unroll
        for (int e = 0; e < 4; e++) o[dn][e] = 0.f;
    float m0v = -1e30f, m1v = -1e30f, l0v = 0.f, l1v = 0.f;

    const int row0 = m0 + rs;      // global query rows (row0, row0+8)

    for (int j0 = 0; j0 <= m0; j0 += 64) {
        const bool diag = (j0 == m0);
        __syncthreads();           // prior iter's smem reads complete

        // ---- stage K (hi/lo, permuted d-cols) ----
#pragma unroll
        for (int i = tid; i < 64 * 16; i += 128) {
            const int row = i >> 4, f4 = i & 15;
            float4 v = *(const float4*)(kb + (size_t)(j0 + row) * 3072 + f4 * 4);
            const int off = row * ALD + (f4 >> 1) * 8 + (f4 & 1);
            float hx = rtf32(v.x), hy = rtf32(v.y), hz = rtf32(v.z), hw = rtf32(v.w);
            Kh[off + 0] = hx; Kl[off + 0] = rtf32(v.x - hx);
            Kh[off + 2] = hy; Kl[off + 2] = rtf32(v.y - hy);
            Kh[off + 4] = hz; Kl[off + 4] = rtf32(v.z - hz);
            Kh[off + 6] = hw; Kl[off + 6] = rtf32(v.w - hw);
        }
        // ---- stage V transposed (hi/lo, permuted key-cols) ----
#pragma unroll
        for (int i = tid; i < 64 * 16; i += 128) {
            const int key = i >> 4, f4 = i & 15;
            float4 v = *(const float4*)(vb + (size_t)(j0 + key) * 3072 + f4 * 4);
            const int j = key & 7;
            const int slot = (key >> 3) * 8 + 2 * (j & 3) + (j >> 2);
            const int d0 = f4 * 4;
            float hx = rtf32(v.x), hy = rtf32(v.y), hz = rtf32(v.z), hw = rtf32(v.w);
            VTh[(d0 + 0) * ALD + slot] = hx; VTl[(d0 + 0) * ALD + slot] = rtf32(v.x - hx);
            VTh[(d0 + 1) * ALD + slot] = hy; VTl[(d0 + 1) * ALD + slot] = rtf32(v.y - hy);
            VTh[(d0 + 2) * ALD + slot] = hz; VTl[(d0 + 2) * ALD + slot] = rtf32(v.z - hz);
            VTh[(d0 + 3) * ALD + slot] = hw; VTl[(d0 + 3) * ALD + slot] = rtf32(v.w - hw);
        }
        __syncthreads();

        // ---- S = Q @ K^T (compensated) ----
        float s[8][4];
#pragma unroll
        for (int n = 0; n < 8; n++)
#pragma unroll
            for (int e = 0; e < 4; e++) s[n][e] = 0.f;

#pragma unroll
        for (int kk = 0; kk < 8; kk++) {
#pragma unroll
            for (int n = 0; n < 8; n++) {
                const int koff = (n * 8 + qr) * ALD + kk * 8 + 2 * qc;
                float2 fh = *(const float2*)(Kh + koff);
                float2 fl = *(const float2*)(Kl + koff);
                uint32_t bhf[2] = { __float_as_uint(fh.x), __float_as_uint(fh.y) };
                uint32_t blf[2] = { __float_as_uint(fl.x), __float_as_uint(fl.y) };
                mma8(s[n], qh[kk], bhf);
                mma8(s[n], qh[kk], blf);
                mma8(s[n], ql[kk], bhf);
            }
        }

        // ---- causal mask (diagonal tile only) ----
        if (diag) {
#pragma unroll
            for (int n = 0; n < 8; n++) {
                const int key = j0 + n * 8 + 2 * qc;
                if (key     > row0)     s[n][0] = -1e30f;
                if (key + 1 > row0)     s[n][1] = -1e30f;
                if (key     > row0 + 8) s[n][2] = -1e30f;
                if (key + 1 > row0 + 8) s[n][3] = -1e30f;
            }
        }

        // ---- online softmax ----
        float mx0 = -1e30f, mx1 = -1e30f;
#pragma unroll
        for (int n = 0; n < 8; n++) {
            mx0 = fmaxf(mx0, fmaxf(s[n][0], s[n][1]));
            mx1 = fmaxf(mx1, fmaxf(s[n][2], s[n][3]));
        }
        mx0 = fmaxf(mx0, __shfl_xor_sync(0xffffffffu, mx0, 1));
        mx0 = fmaxf(mx0, __shfl_xor_sync(0xffffffffu, mx0, 2));
        mx1 = fmaxf(mx1, __shfl_xor_sync(0xffffffffu, mx1, 1));
        mx1 = fmaxf(mx1, __shfl_xor_sync(0xffffffffu, mx1, 2));
        const float mn0 = fmaxf(m0v, mx0);
        const float mn1 = fmaxf(m1v, mx1);
        const float c0 = __expf(m0v - mn0);
        const float c1 = __expf(m1v - mn1);
        m0v = mn0; m1v = mn1;
        l0v *= c0;  l1v *= c1;
#pragma unroll
        for (int dn = 0; dn < 8; dn++) {
            o[dn][0] *= c0; o[dn][1] *= c0;
            o[dn][2] *= c1; o[dn][3] *= c1;
        }

        float ps0 = 0.f, ps1 = 0.f;
#pragma unroll
        for (int n = 0; n < 8; n++) {
            float p0 = __expf(s[n][0] - mn0);
            float p1 = __expf(s[n][1] - mn0);
            float p2 = __expf(s[n][2] - mn1);
            float p3 = __expf(s[n][3] - mn1);
            ps0 += p0 + p1;
            ps1 += p2 + p3;
            // store P to Ps (own rows only -> warp-local)
            *(float2*)(Qs + rs * ALD + n * 8 + 2 * qc)       = make_float2(p0, p1);
            *(float2*)(Qs + (rs + 8) * ALD + n * 8 + 2 * qc) = make_float2(p2, p3);
        }
        ps0 += __shfl_xor_sync(0xffffffffu, ps0, 1);
        ps0 += __shfl_xor_sync(0xffffffffu, ps0, 2);
        ps1 += __shfl_xor_sync(0xffffffffu, ps1, 1);
        ps1 += __shfl_xor_sync(0xffffffffu, ps1, 2);
        l0v += ps0; l1v += ps1;
        __syncwarp();

        // ---- O += P @ V (compensated) ----
#pragma unroll
        for (int kk = 0; kk < 8; kk++) {
            uint32_t pah[4], pal[4];
            split_tf(Qs[rs * ALD + kk * 8 + qc],            pah[0], pal[0]);
            split_tf(Qs[(rs + 8) * ALD + kk * 8 + qc],      pah[1], pal[1]);
            split_tf(Qs[rs * ALD + kk * 8 + qc + 4],        pah[2], pal[2]);
            split_tf(Qs[(rs + 8) * ALD + kk * 8 + qc + 4],  pah[3], pal[3]);
#pragma unroll
            for (int dn = 0; dn < 8; dn++) {
                const int voff = (dn * 8 + qr) * ALD + kk * 8 + 2 * qc;
                float2 vh = *(const float2*)(VTh + voff);
                float2 vl = *(const float2*)(VTl + voff);
                uint32_t bvh[2] = { __float_as_uint(vh.x), __float_as_uint(vh.y) };
                uint32_t bvl[2] = { __float_as_uint(vl.x), __float_as_uint(vl.y) };
                mma8(o[dn], pah, bvh);
                mma8(o[dn], pah, bvl);
                mma8(o[dn], pal, bvh);
            }
        }
    }

    // ---- epilogue ----
    const float i0 = 1.f / l0v;
    const float i1 = 1.f / l1v;
    float* o0 = out + ((size_t)b * T_ + row0) * C_ + h * 64;
    float* o1 = o0 + 8 * C_;
#pragma unroll
    for (int dn = 0; dn < 8; dn++) {
        *(float2*)(o0 + dn * 8 + 2 * qc) = make_float2(o[dn][0] * i0, o[dn][1] * i0);
        *(float2*)(o1 + dn * 8 + 2 * qc) = make_float2(o[dn][2] * i1, o[dn][3] * i1);
    }
}

// ---------------------------------------------------------------------------
// Depthwise causal conv (K=4) + bias + residual
// ---------------------------------------------------------------------------
__global__ void __launch_bounds__(256)
conv_residual(const float* __restrict__ x, const float* __restrict__ w,
              const float* __restrict__ bias, float* __restrict__ y)
{
    int idx = blockIdx.x * blockDim.x + threadIdx.x;
    if (idx >= MTOK * C_) return;
    const int c = idx & (C_ - 1);
    const int t = (idx >> 10) & (T_ - 1);

    float s = bias[c] + x[idx];
#pragma unroll
    for (int k = 0; k < 4; k++) {
        int ts = t + k - 3;
        if (ts >= 0) s += w[c * 4 + k] * x[idx + (k - 3) * C_];
    }
    y[idx] = s;
}

// ---------------------------------------------------------------------------
// Launch
// ---------------------------------------------------------------------------
extern "C" void kernel_launch(void* const* d_in, const int* in_sizes, int n_in,
                              void* d_out, int out_size)
{
    const float* x     = (const float*)d_in[0];
    const float* Wqkv  = (const float*)d_in[1];
    const float* Wout  = (const float*)d_in[2];
    const float* convw = (const float*)d_in[3];
    const float* convb = (const float*)d_in[4];
    float* out = (float*)d_out;

    float *qkv, *attn, *conv;
    cudaGetSymbolAddress((void**)&qkv,  g_qkv);
    cudaGetSymbolAddress((void**)&attn, g_attn);
    cudaGetSymbolAddress((void**)&conv, g_conv);

    cudaFuncSetAttribute(flash_attn_mma,
                         cudaFuncAttributeMaxDynamicSharedMemorySize,
                         ATT_SMEM_BYTES);

    // 1) QKV projection: [8192,1024] @ [3072,1024]^T
    sgemm_nt<<<dim3(3072 / 128, MTOK / 128), 256>>>(x, Wqkv, qkv, MTOK, 3072, 1024);

    // 2) Causal flash attention on tensor cores (tf32 compensated)
    flash_attn_mma<<<dim3(T_ / 64, B_ * H_), 128, ATT_SMEM_BYTES>>>(qkv, attn);

    // 3) Depthwise causal conv + residual
    conv_residual<<<(MTOK * C_) / 256, 256>>>(attn, convw, convb, conv);

    // 4) Output projection: [8192,1024] @ [1024,1024]^T
    sgemm_nt<<<dim3(1024 / 128, MTOK / 128), 256>>>(conv, Wout, out, MTOK, 1024, 1024);
}

// round 5
// speedup vs baseline: 2.7437x; 2.3441x over previous
#include <cuda_runtime.h>
#include <cuda_fp16.h>
#include <cstdint>
#include <cstddef>

#define B_   4
#define T_   2048
#define C_   1024
#define H_   16
#define MTOK 8192

// ---------------------------------------------------------------------------
// Scratch
// ---------------------------------------------------------------------------
__device__ __half g_xh[(size_t)MTOK * C_],     g_xl[(size_t)MTOK * C_];
__device__ __half g_wqh[(size_t)3 * C_ * C_],  g_wql[(size_t)3 * C_ * C_];
__device__ __half g_woh[(size_t)C_ * C_],      g_wol[(size_t)C_ * C_];
__device__ __half g_qh[(size_t)MTOK * 3 * C_], g_ql[(size_t)MTOK * 3 * C_];
__device__ __half g_ch[(size_t)MTOK * C_],     g_cl[(size_t)MTOK * C_];
__device__ float  g_attn[(size_t)MTOK * C_];

// ---------------------------------------------------------------------------
// Helpers
// ---------------------------------------------------------------------------
__device__ __forceinline__ uint32_t su32(const void* p) {
    uint32_t a;
    asm("{ .reg .u64 t; cvta.to.shared.u64 t, %1; cvt.u32.u64 %0, t; }"
        : "=r"(a) : "l"(p));
    return a;
}
__device__ __forceinline__ void cpa16(uint32_t dst, const void* src) {
    asm volatile("cp.async.cg.shared.global [%0], [%1], 16;" :: "r"(dst), "l"(src));
}
#define CP_COMMIT() asm volatile("cp.async.commit_group;" ::: "memory")

__device__ __forceinline__ void ldm4(uint32_t* r, uint32_t a) {
    asm volatile("ldmatrix.sync.aligned.m8n8.x4.shared.b16 {%0,%1,%2,%3}, [%4];"
                 : "=r"(r[0]), "=r"(r[1]), "=r"(r[2]), "=r"(r[3]) : "r"(a));
}
__device__ __forceinline__ void ldm4t(uint32_t* r, uint32_t a) {
    asm volatile("ldmatrix.sync.aligned.m8n8.x4.trans.shared.b16 {%0,%1,%2,%3}, [%4];"
                 : "=r"(r[0]), "=r"(r[1]), "=r"(r[2]), "=r"(r[3]) : "r"(a));
}
__device__ __forceinline__ void mma16(float* d, const uint32_t* a, const uint32_t* b) {
    asm volatile(
        "mma.sync.aligned.m16n8k16.row.col.f32.f16.f16.f32 "
        "{%0,%1,%2,%3}, {%4,%5,%6,%7}, {%8,%9}, {%0,%1,%2,%3};"
        : "+f"(d[0]), "+f"(d[1]), "+f"(d[2]), "+f"(d[3])
        : "r"(a[0]), "r"(a[1]), "r"(a[2]), "r"(a[3]), "r"(b[0]), "r"(b[1]));
}
__device__ __forceinline__ void split2(float x, float y, uint32_t& h, uint32_t& l) {
    __half2 hh = __float22half2_rn(make_float2(x, y));
    float rx = x - __half2float(__low2half(hh));
    float ry = y - __half2float(__high2half(hh));
    __half2 ll = __float22half2_rn(make_float2(rx, ry));
    h = *reinterpret_cast<uint32_t*>(&hh);
    l = *reinterpret_cast<uint32_t*>(&ll);
}

// ---------------------------------------------------------------------------
// fp32 -> fp16 hi/lo split
// ---------------------------------------------------------------------------
__global__ void __launch_bounds__(256)
split_pair(const float2* __restrict__ in, __half2* __restrict__ oh,
           __half2* __restrict__ ol, int n2)
{
    int i = blockIdx.x * blockDim.x + threadIdx.x;
    if (i >= n2) return;
    float2 v = in[i];
    uint32_t h, l;
    split2(v.x, v.y, h, l);
    oh[i] = *reinterpret_cast<__half2*>(&h);
    ol[i] = *reinterpret_cast<__half2*>(&l);
}

// ---------------------------------------------------------------------------
// fp16-compensated GEMM (NT): C[M,N] = A @ B^T, K=1024, M,N mult of 128.
// 128x128 tile, BK=64, 8 warps (2m x 4n), 2-stage cp.async pipeline.
// SPLIT: emit half hi/lo (QKV path; scale cols<1024 by 0.125).
// ---------------------------------------------------------------------------
template<int NOUT, bool SPLIT>
__global__ void __launch_bounds__(256, 1)
gemm16(const __half* __restrict__ Ah, const __half* __restrict__ Al,
       const __half* __restrict__ Bh, const __half* __restrict__ Bl,
       float* __restrict__ outF, __half* __restrict__ outH,
       __half* __restrict__ outL)
{
    extern __shared__ char smx[];
    const uint32_t smB = su32(smx);
    const int tid  = threadIdx.x;
    const int lane = tid & 31;
    const int wid  = tid >> 5;
    const int wm   = wid & 1;
    const int wn   = wid >> 1;
    const int lr   = lane & 7, g = lane >> 3;
    const int qr   = lane >> 2, qc = lane & 3;
    const int bm   = blockIdx.y * 128;
    const int bn   = blockIdx.x * 128;

    int rows[4], cs[4];
    uint32_t dstOff[4];
#pragma unroll
    for (int q = 0; q < 4; q++) {
        int id = tid * 4 + q;
        rows[q] = id >> 3;
        cs[q]   = id & 7;
        dstOff[q] = rows[q] * 128 + ((cs[q] ^ (rows[q] & 7)) << 4);
    }

    auto stage = [&](int k0, int s) {
        const uint32_t bb = smB + s * 65536;
#pragma unroll
        for (int q = 0; q < 4; q++) {
            const size_t ao = (size_t)(bm + rows[q]) * 1024 + k0 + cs[q] * 8;
            const size_t bo = (size_t)(bn + rows[q]) * 1024 + k0 + cs[q] * 8;
            cpa16(bb + dstOff[q],         Ah + ao);
            cpa16(bb + 16384 + dstOff[q], Al + ao);
            cpa16(bb + 32768 + dstOff[q], Bh + bo);
            cpa16(bb + 49152 + dstOff[q], Bl + bo);
        }
        CP_COMMIT();
    };

    float c[4][4][4];
#pragma unroll
    for (int i = 0; i < 4; i++)
#pragma unroll
        for (int j = 0; j < 4; j++)
#pragma unroll
            for (int e = 0; e < 4; e++) c[i][j][e] = 0.f;

    const int aRow = lr + ((g & 1) << 3), aCh = g >> 1;
    const int bRow = lr + ((g >> 1) << 3), bCh = g & 1;

    stage(0, 0);

    for (int ki = 0; ki < 16; ki++) {
        if (ki < 15) {
            stage((ki + 1) * 64, (ki + 1) & 1);
            asm volatile("cp.async.wait_group 1;" ::: "memory");
        } else {
            asm volatile("cp.async.wait_group 0;" ::: "memory");
        }
        __syncthreads();
        const uint32_t st = smB + (ki & 1) * 65536;

#pragma unroll
        for (int kk = 0; kk < 4; kk++) {
            uint32_t ah[4][4], al[4][4];
#pragma unroll
            for (int i = 0; i < 4; i++) {
                uint32_t a = st + (wm * 64 + i * 16 + aRow) * 128 +
                             (((2 * kk + aCh) ^ lr) << 4);
                ldm4(ah[i], a);
                ldm4(al[i], a + 16384);
            }
#pragma unroll
            for (int jp = 0; jp < 2; jp++) {
                uint32_t bh4[4], bl4[4];
                uint32_t a = st + 32768 + (wn * 32 + jp * 16 + bRow) * 128 +
                             (((2 * kk + bCh) ^ lr) << 4);
                ldm4(bh4, a);
                ldm4(bl4, a + 16384);
#pragma unroll
                for (int i = 0; i < 4; i++) {
                    mma16(c[i][2 * jp],     ah[i], bh4);
                    mma16(c[i][2 * jp],     ah[i], bl4);
                    mma16(c[i][2 * jp],     al[i], bh4);
                    mma16(c[i][2 * jp + 1], ah[i], bh4 + 2);
                    mma16(c[i][2 * jp + 1], ah[i], bl4 + 2);
                    mma16(c[i][2 * jp + 1], al[i], bh4 + 2);
                }
            }
        }
        __syncthreads();
    }

#pragma unroll
    for (int i = 0; i < 4; i++) {
#pragma unroll
        for (int j = 0; j < 4; j++) {
            const int row = bm + wm * 64 + i * 16 + qr;
            const int col = bn + wn * 32 + j * 8 + 2 * qc;
            if (SPLIT) {
                const float sc = (col < 1024) ? 0.125f : 1.f;
                uint32_t h0, l0, h1, l1;
                split2(c[i][j][0] * sc, c[i][j][1] * sc, h0, l0);
                split2(c[i][j][2] * sc, c[i][j][3] * sc, h1, l1);
                *(uint32_t*)(outH + (size_t)row * NOUT + col) = h0;
                *(uint32_t*)(outL + (size_t)row * NOUT + col) = l0;
                *(uint32_t*)(outH + (size_t)(row + 8) * NOUT + col) = h1;
                *(uint32_t*)(outL + (size_t)(row + 8) * NOUT + col) = l1;
            } else {
                *(float2*)(outF + (size_t)row * NOUT + col) =
                    make_float2(c[i][j][0], c[i][j][1]);
                *(float2*)(outF + (size_t)(row + 8) * NOUT + col) =
                    make_float2(c[i][j][2], c[i][j][3]);
            }
        }
    }
}

// ---------------------------------------------------------------------------
// Flash attention (causal), fp16 compensated, register-resident P.
// Block 64 queries x 4 warps; KV tiles of 64, double-buffered cp.async.
// ---------------------------------------------------------------------------
#define FA_SMEM 81920

__global__ void __launch_bounds__(128, 2)
flash16(const __half* __restrict__ qh, const __half* __restrict__ ql,
        float* __restrict__ out)
{
    extern __shared__ char smx[];
    const uint32_t smB = su32(smx);
    const int tid  = threadIdx.x;
    const int w    = tid >> 5;
    const int lane = tid & 31;
    const int lr   = lane & 7, g = lane >> 3;
    const int qr   = lane >> 2, qc = lane & 3;
    const int bhx  = blockIdx.y;
    const int b    = bhx >> 4;
    const int hh   = bhx & 15;
    const int m0   = blockIdx.x * 64;

    const size_t base = (size_t)b * T_ * 3072 + hh * 64;
    const __half* qhp = qh + base;
    const __half* qlp = ql + base;
    const __half* khp = qhp + 1024;
    const __half* klp = qlp + 1024;
    const __half* vhp = qhp + 2048;
    const __half* vlp = qlp + 2048;

    int sRow[4], sC[4];
    uint32_t sDst[4];
#pragma unroll
    for (int q = 0; q < 4; q++) {
        int id = tid * 4 + q;
        sRow[q] = id >> 3;
        sC[q]   = id & 7;
        sDst[q] = sRow[q] * 128 + ((sC[q] ^ (sRow[q] & 7)) << 4);
    }

    auto stage_kv = [&](int j0, int s) {
        const uint32_t bb = smB + 16384 + s * 32768;
#pragma unroll
        for (int q = 0; q < 4; q++) {
            const size_t so = (size_t)(j0 + sRow[q]) * 3072 + sC[q] * 8;
            cpa16(bb + sDst[q],         khp + so);
            cpa16(bb + 8192  + sDst[q], klp + so);
            cpa16(bb + 16384 + sDst[q], vhp + so);
            cpa16(bb + 24576 + sDst[q], vlp + so);
        }
        CP_COMMIT();
    };

#pragma unroll
    for (int q = 0; q < 4; q++) {
        const size_t so = (size_t)(m0 + sRow[q]) * 3072 + sC[q] * 8;
        cpa16(smB + sDst[q],        qhp + so);
        cpa16(smB + 8192 + sDst[q], qlp + so);
    }
    CP_COMMIT();
    stage_kv(0, 0);
    asm volatile("cp.async.wait_group 1;" ::: "memory");
    __syncthreads();

    const int aRow = lr + ((g & 1) << 3), aCh = g >> 1;    // A (Q/P) pattern
    const int kRow = lr + ((g >> 1) << 3), kCh = g & 1;    // B (K) pattern
    uint32_t qfh[4][4], qfl[4][4];
#pragma unroll
    for (int kk = 0; kk < 4; kk++) {
        uint32_t a = smB + (w * 16 + aRow) * 128 + (((2 * kk + aCh) ^ lr) << 4);
        ldm4(qfh[kk], a);
        ldm4(qfl[kk], a + 8192);
    }

    float o_[8][4];
#pragma unroll
    for (int n = 0; n < 8; n++)
#pragma unroll
        for (int e = 0; e < 4; e++) o_[n][e] = 0.f;
    float m0v = -1e30f, m1v = -1e30f, l0v = 0.f, l1v = 0.f;
    const int row0 = m0 + w * 16 + qr;

    for (int j0 = 0; j0 <= m0; j0 += 64) {
        const int st = (j0 >> 6) & 1;
        if (j0 + 64 <= m0) {
            stage_kv(j0 + 64, st ^ 1);
            asm volatile("cp.async.wait_group 1;" ::: "memory");
        } else {
            asm volatile("cp.async.wait_group 0;" ::: "memory");
        }
        __syncthreads();
        const uint32_t KB = smB + 16384 + st * 32768;
        const uint32_t VB = KB + 16384;

        float s_[8][4];
#pragma unroll
        for (int n = 0; n < 8; n++)
#pragma unroll
            for (int e = 0; e < 4; e++) s_[n][e] = 0.f;

#pragma unroll
        for (int kk = 0; kk < 4; kk++) {
#pragma unroll
            for (int np = 0; np < 4; np++) {
                uint32_t kh4[4], kl4[4];
                uint32_t a = KB + np * 2048 + kRow * 128 +
                             (((2 * kk + kCh) ^ lr) << 4);
                ldm4(kh4, a);
                ldm4(kl4, a + 8192);
                mma16(s_[2 * np],     qfh[kk], kh4);
                mma16(s_[2 * np],     qfh[kk], kl4);
                mma16(s_[2 * np],     qfl[kk], kh4);
                mma16(s_[2 * np + 1], qfh[kk], kh4 + 2);
                mma16(s_[2 * np + 1], qfh[kk], kl4 + 2);
                mma16(s_[2 * np + 1], qfl[kk], kh4 + 2);
            }
        }

        if (j0 == m0) {
#pragma unroll
            for (int n = 0; n < 8; n++) {
                const int key = j0 + n * 8 + 2 * qc;
                if (key     > row0)     s_[n][0] = -1e30f;
                if (key + 1 > row0)     s_[n][1] = -1e30f;
                if (key     > row0 + 8) s_[n][2] = -1e30f;
                if (key + 1 > row0 + 8) s_[n][3] = -1e30f;
            }
        }

        float mx0 = -1e30f, mx1 = -1e30f;
#pragma unroll
        for (int n = 0; n < 8; n++) {
            mx0 = fmaxf(mx0, fmaxf(s_[n][0], s_[n][1]));
            mx1 = fmaxf(mx1, fmaxf(s_[n][2], s_[n][3]));
        }
        mx0 = fmaxf(mx0, __shfl_xor_sync(0xffffffffu, mx0, 1));
        mx0 = fmaxf(mx0, __shfl_xor_sync(0xffffffffu, mx0, 2));
        mx1 = fmaxf(mx1, __shfl_xor_sync(0xffffffffu, mx1, 1));
        mx1 = fmaxf(mx1, __shfl_xor_sync(0xffffffffu, mx1, 2));
        const float mn0 = fmaxf(m0v, mx0);
        const float mn1 = fmaxf(m1v, mx1);
        const float c0 = __expf(m0v - mn0);
        const float c1 = __expf(m1v - mn1);
        m0v = mn0; m1v = mn1;
        l0v *= c0;  l1v *= c1;
#pragma unroll
        for (int n = 0; n < 8; n++) {
            o_[n][0] *= c0; o_[n][1] *= c0;
            o_[n][2] *= c1; o_[n][3] *= c1;
        }

        uint32_t pAh[8], pAl[8], pBh[8], pBl[8];
        float ps0 = 0.f, ps1 = 0.f;
#pragma unroll
        for (int n = 0; n < 8; n++) {
            float p0 = __expf(s_[n][0] - mn0);
            float p1 = __expf(s_[n][1] - mn0);
            float p2 = __expf(s_[n][2] - mn1);
            float p3 = __expf(s_[n][3] - mn1);
            ps0 += p0 + p1;
            ps1 += p2 + p3;
            split2(p0, p1, pAh[n], pAl[n]);
            split2(p2, p3, pBh[n], pBl[n]);
        }
        ps0 += __shfl_xor_sync(0xffffffffu, ps0, 1);
        ps0 += __shfl_xor_sync(0xffffffffu, ps0, 2);
        ps1 += __shfl_xor_sync(0xffffffffu, ps1, 1);
        ps1 += __shfl_xor_sync(0xffffffffu, ps1, 2);
        l0v += ps0; l1v += ps1;

#pragma unroll
        for (int kk = 0; kk < 4; kk++) {
            uint32_t ah4[4] = { pAh[2 * kk], pBh[2 * kk],
                                pAh[2 * kk + 1], pBh[2 * kk + 1] };
            uint32_t al4[4] = { pAl[2 * kk], pBl[2 * kk],
                                pAl[2 * kk + 1], pBl[2 * kk + 1] };
#pragma unroll
            for (int np = 0; np < 4; np++) {
                uint32_t vh4[4], vl4[4];
                uint32_t a = VB + kk * 2048 + aRow * 128 +
                             (((2 * np + aCh) ^ lr) << 4);
                ldm4t(vh4, a);
                ldm4t(vl4, a + 8192);
                mma16(o_[2 * np],     ah4, vh4);
                mma16(o_[2 * np],     ah4, vl4);
                mma16(o_[2 * np],     al4, vh4);
                mma16(o_[2 * np + 1], ah4, vh4 + 2);
                mma16(o_[2 * np + 1], ah4, vl4 + 2);
                mma16(o_[2 * np + 1], al4, vh4 + 2);
            }
        }
        __syncthreads();
    }

    const float i0 = 1.f / l0v;
    const float i1 = 1.f / l1v;
    float* o0 = out + ((size_t)b * T_ + row0) * C_ + hh * 64;
    float* o1 = o0 + 8 * C_;
#pragma unroll
    for (int n = 0; n < 8; n++) {
        *(float2*)(o0 + n * 8 + 2 * qc) = make_float2(o_[n][0] * i0, o_[n][1] * i0);
        *(float2*)(o1 + n * 8 + 2 * qc) = make_float2(o_[n][2] * i1, o_[n][3] * i1);
    }
}

// ---------------------------------------------------------------------------
// Depthwise causal conv (K=4) + bias + residual -> fp16 hi/lo
// ---------------------------------------------------------------------------
__global__ void __launch_bounds__(256)
conv_split(const float* __restrict__ x, const float* __restrict__ w,
           const float* __restrict__ bias, __half* __restrict__ yh,
           __half* __restrict__ yl)
{
    int i2 = blockIdx.x * blockDim.x + threadIdx.x;
    if (i2 >= MTOK * C_ / 2) return;
    const int idx = i2 * 2;
    const int c = idx & (C_ - 1);
    const int t = (idx >> 10) & (T_ - 1);

    float s0 = bias[c]     + x[idx];
    float s1 = bias[c + 1] + x[idx + 1];
#pragma unroll
    for (int k = 0; k < 4; k++) {
        int ts = t + k - 3;
        if (ts >= 0) {
            s0 += w[c * 4 + k]       * x[idx + (k - 3) * C_];
            s1 += w[(c + 1) * 4 + k] * x[idx + 1 + (k - 3) * C_];
        }
    }
    uint32_t h, l;
    split2(s0, s1, h, l);
    *(uint32_t*)(yh + idx) = h;
    *(uint32_t*)(yl + idx) = l;
}

// ---------------------------------------------------------------------------
// Launch
// ---------------------------------------------------------------------------
extern "C" void kernel_launch(void* const* d_in, const int* in_sizes, int n_in,
                              void* d_out, int out_size)
{
    const float* x     = (const float*)d_in[0];
    const float* Wqkv  = (const float*)d_in[1];
    const float* Wout  = (const float*)d_in[2];
    const float* convw = (const float*)d_in[3];
    const float* convb = (const float*)d_in[4];
    float* out = (float*)d_out;

    __half *xh, *xl, *wqh, *wql, *woh, *wol, *qh, *ql, *ch, *cl;
    float* attn;
    cudaGetSymbolAddress((void**)&xh,  g_xh);
    cudaGetSymbolAddress((void**)&xl,  g_xl);
    cudaGetSymbolAddress((void**)&wqh, g_wqh);
    cudaGetSymbolAddress((void**)&wql, g_wql);
    cudaGetSymbolAddress((void**)&woh, g_woh);
    cudaGetSymbolAddress((void**)&wol, g_wol);
    cudaGetSymbolAddress((void**)&qh,  g_qh);
    cudaGetSymbolAddress((void**)&ql,  g_ql);
    cudaGetSymbolAddress((void**)&ch,  g_ch);
    cudaGetSymbolAddress((void**)&cl,  g_cl);
    cudaGetSymbolAddress((void**)&attn, g_attn);

    constexpr int GSM = 131072;
    cudaFuncSetAttribute(gemm16<3072, true>,
                         cudaFuncAttributeMaxDynamicSharedMemorySize, GSM);
    cudaFuncSetAttribute(gemm16<1024, false>,
                         cudaFuncAttributeMaxDynamicSharedMemorySize, GSM);
    cudaFuncSetAttribute(flash16,
                         cudaFuncAttributeMaxDynamicSharedMemorySize, FA_SMEM);

    // 0) split inputs
    split_pair<<<MTOK * C_ / 2 / 256, 256>>>((const float2*)x,
                                             (__half2*)xh, (__half2*)xl,
                                             MTOK * C_ / 2);
    split_pair<<<3 * C_ * C_ / 2 / 256, 256>>>((const float2*)Wqkv,
                                               (__half2*)wqh, (__half2*)wql,
                                               3 * C_ * C_ / 2);
    split_pair<<<C_ * C_ / 2 / 256, 256>>>((const float2*)Wout,
                                           (__half2*)woh, (__half2*)wol,
                                           C_ * C_ / 2);

    // 1) QKV projection (emits split hi/lo, Q pre-scaled)
    gemm16<3072, true><<<dim3(24, 64), 256, GSM>>>(xh, xl, wqh, wql,
                                                   nullptr, qh, ql);

    // 2) attention
    flash16<<<dim3(T_ / 64, B_ * H_), 128, FA_SMEM>>>(qh, ql, attn);

    // 3) conv + residual -> split
    conv_split<<<MTOK * C_ / 2 / 256, 256>>>(attn, convw, convb, ch, cl);

    // 4) output projection
    gemm16<1024, false><<<dim3(8, 64), 256, GSM>>>(ch, cl, woh, wol,
                                                   out, nullptr, nullptr);
}

// round 8
// speedup vs baseline: 2.9689x; 1.0821x over previous
#include <cuda_runtime.h>
#include <cuda_fp16.h>
#include <cstdint>
#include <cstddef>

#define B_   4
#define T_   2048
#define C_   1024
#define H_   16
#define MTOK 8192

// ---------------------------------------------------------------------------
// Scratch
// ---------------------------------------------------------------------------
__device__ __half g_xh[(size_t)MTOK * C_],     g_xl[(size_t)MTOK * C_];
__device__ __half g_wqh[(size_t)3 * C_ * C_],  g_wql[(size_t)3 * C_ * C_];
__device__ __half g_woh[(size_t)C_ * C_],      g_wol[(size_t)C_ * C_];
__device__ __half g_qh[(size_t)MTOK * 3 * C_], g_ql[(size_t)MTOK * 3 * C_];
__device__ __half g_ch[(size_t)MTOK * C_],     g_cl[(size_t)MTOK * C_];
__device__ float  g_attn[(size_t)MTOK * C_];

// ---------------------------------------------------------------------------
// Helpers
// ---------------------------------------------------------------------------
__device__ __forceinline__ uint32_t su32(const void* p) {
    uint32_t a;
    asm("{ .reg .u64 t; cvta.to.shared.u64 t, %1; cvt.u32.u64 %0, t; }"
        : "=r"(a) : "l"(p));
    return a;
}
__device__ __forceinline__ void cpa16(uint32_t dst, const void* src) {
    asm volatile("cp.async.cg.shared.global [%0], [%1], 16;" :: "r"(dst), "l"(src));
}
#define CP_COMMIT() asm volatile("cp.async.commit_group;" ::: "memory")

__device__ __forceinline__ void ldm4(uint32_t* r, uint32_t a) {
    asm volatile("ldmatrix.sync.aligned.m8n8.x4.shared.b16 {%0,%1,%2,%3}, [%4];"
                 : "=r"(r[0]), "=r"(r[1]), "=r"(r[2]), "=r"(r[3]) : "r"(a));
}
__device__ __forceinline__ void ldm4t(uint32_t* r, uint32_t a) {
    asm volatile("ldmatrix.sync.aligned.m8n8.x4.trans.shared.b16 {%0,%1,%2,%3}, [%4];"
                 : "=r"(r[0]), "=r"(r[1]), "=r"(r[2]), "=r"(r[3]) : "r"(a));
}
__device__ __forceinline__ void mma16(float* d, const uint32_t* a, const uint32_t* b) {
    asm volatile(
        "mma.sync.aligned.m16n8k16.row.col.f32.f16.f16.f32 "
        "{%0,%1,%2,%3}, {%4,%5,%6,%7}, {%8,%9}, {%0,%1,%2,%3};"
        : "+f"(d[0]), "+f"(d[1]), "+f"(d[2]), "+f"(d[3])
        : "r"(a[0]), "r"(a[1]), "r"(a[2]), "r"(a[3]), "r"(b[0]), "r"(b[1]));
}
__device__ __forceinline__ void split2(float x, float y, uint32_t& h, uint32_t& l) {
    __half2 hh = __float22half2_rn(make_float2(x, y));
    float rx = x - __half2float(__low2half(hh));
    float ry = y - __half2float(__high2half(hh));
    __half2 ll = __float22half2_rn(make_float2(rx, ry));
    h = *reinterpret_cast<uint32_t*>(&hh);
    l = *reinterpret_cast<uint32_t*>(&ll);
}

// ---------------------------------------------------------------------------
// fp32 -> fp16 hi/lo split
// ---------------------------------------------------------------------------
__global__ void __launch_bounds__(256)
split_pair(const float2* __restrict__ in, __half2* __restrict__ oh,
           __half2* __restrict__ ol, int n2)
{
    int i = blockIdx.x * blockDim.x + threadIdx.x;
    if (i >= n2) return;
    float2 v = in[i];
    uint32_t h, l;
    split2(v.x, v.y, h, l);
    oh[i] = *reinterpret_cast<__half2*>(&h);
    ol[i] = *reinterpret_cast<__half2*>(&l);
}

// ---------------------------------------------------------------------------
// fp16-compensated GEMM v2 (NT): 128x128 tile, BK=32, 2 CTAs/SM.
// Smem/stage 32KB: Ah[128][32] | Al | Bh[128][32] | Bl (64B rows,
// chunk swizzle ch ^ ((row>>1)&3) -> conflict-free ldmatrix).
// Pass order hh -> hl -> lh with A-lo reusing A-hi registers.
// ---------------------------------------------------------------------------
#define GSM 65536

template<int NOUT, bool SPLIT>
__global__ void __launch_bounds__(256, 2)
gemm16(const __half* __restrict__ Ah, const __half* __restrict__ Al,
       const __half* __restrict__ Bh, const __half* __restrict__ Bl,
       float* __restrict__ outF, __half* __restrict__ outH,
       __half* __restrict__ outL)
{
    extern __shared__ char smx[];
    const uint32_t smB = su32(smx);
    const int tid  = threadIdx.x;
    const int lane = tid & 31;
    const int wid  = tid >> 5;
    const int wm   = wid & 1;
    const int wn   = wid >> 1;
    const int lr   = lane & 7, g = lane >> 3;
    const int qr   = lane >> 2, qc = lane & 3;
    const int bm   = blockIdx.y * 128;
    const int bn   = blockIdx.x * 128;

    const int aCh = g >> 1;
    const int bCh = g & 1;
    const int aRowF = lr + ((g & 1) << 3);
    const int bRowF = lr + ((g >> 1) << 3);

    const int id0 = tid * 2, id1 = tid * 2 + 1;
    const int r0 = id0 >> 2, c0 = id0 & 3;
    const int r1 = id1 >> 2, c1 = id1 & 3;
    const uint32_t o0 = r0 * 64 + (((c0 ^ ((r0 >> 1) & 3))) << 4);
    const uint32_t o1 = r1 * 64 + (((c1 ^ ((r1 >> 1) & 3))) << 4);

    auto stage = [&](int k0, int s) {
        const uint32_t bb = smB + s * 32768;
        const size_t a0 = (size_t)(bm + r0) * 1024 + k0 + c0 * 8;
        const size_t a1 = (size_t)(bm + r1) * 1024 + k0 + c1 * 8;
        const size_t b0 = (size_t)(bn + r0) * 1024 + k0 + c0 * 8;
        const size_t b1 = (size_t)(bn + r1) * 1024 + k0 + c1 * 8;
        cpa16(bb + o0,         Ah + a0);  cpa16(bb + o1,         Ah + a1);
        cpa16(bb + 8192 + o0,  Al + a0);  cpa16(bb + 8192 + o1,  Al + a1);
        cpa16(bb + 16384 + o0, Bh + b0);  cpa16(bb + 16384 + o1, Bh + b1);
        cpa16(bb + 24576 + o0, Bl + b0);  cpa16(bb + 24576 + o1, Bl + b1);
        CP_COMMIT();
    };

    float c[4][4][4];
#pragma unroll
    for (int i = 0; i < 4; i++)
#pragma unroll
        for (int j = 0; j < 4; j++)
#pragma unroll
            for (int e = 0; e < 4; e++) c[i][j][e] = 0.f;

    stage(0, 0);

    for (int ki = 0; ki < 32; ki++) {
        if (ki < 31) {
            stage((ki + 1) * 32, (ki + 1) & 1);
            asm volatile("cp.async.wait_group 1;" ::: "memory");
        } else {
            asm volatile("cp.async.wait_group 0;" ::: "memory");
        }
        __syncthreads();
        const uint32_t st = smB + (ki & 1) * 32768;

#pragma unroll
        for (int kk = 0; kk < 2; kk++) {
            uint32_t af[4][4];
#pragma unroll
            for (int i = 0; i < 4; i++) {
                const int row = wm * 64 + i * 16 + aRowF;
                ldm4(af[i], st + row * 64 +
                     (((2 * kk + aCh) ^ ((row >> 1) & 3)) << 4));
            }
            uint32_t bh4[2][4], bl4[2][4];
#pragma unroll
            for (int jp = 0; jp < 2; jp++) {
                const int row = wn * 32 + jp * 16 + bRowF;
                const uint32_t a = st + 16384 + row * 64 +
                                   (((2 * kk + bCh) ^ ((row >> 1) & 3)) << 4);
                ldm4(bh4[jp], a);
                ldm4(bl4[jp], a + 8192);
            }
#pragma unroll
            for (int jp = 0; jp < 2; jp++)
#pragma unroll
                for (int i = 0; i < 4; i++) {
                    mma16(c[i][2 * jp],     af[i], bh4[jp]);
                    mma16(c[i][2 * jp + 1], af[i], bh4[jp] + 2);
                }
#pragma unroll
            for (int jp = 0; jp < 2; jp++)
#pragma unroll
                for (int i = 0; i < 4; i++) {
                    mma16(c[i][2 * jp],     af[i], bl4[jp]);
                    mma16(c[i][2 * jp + 1], af[i], bl4[jp] + 2);
                }
#pragma unroll
            for (int i = 0; i < 4; i++) {
                const int row = wm * 64 + i * 16 + aRowF;
                ldm4(af[i], st + 8192 + row * 64 +
                     (((2 * kk + aCh) ^ ((row >> 1) & 3)) << 4));
            }
#pragma unroll
            for (int jp = 0; jp < 2; jp++)
#pragma unroll
                for (int i = 0; i < 4; i++) {
                    mma16(c[i][2 * jp],     af[i], bh4[jp]);
                    mma16(c[i][2 * jp + 1], af[i], bh4[jp] + 2);
                }
        }
        __syncthreads();
    }

#pragma unroll
    for (int i = 0; i < 4; i++) {
#pragma unroll
        for (int j = 0; j < 4; j++) {
            const int row = bm + wm * 64 + i * 16 + qr;
            const int col = bn + wn * 32 + j * 8 + 2 * qc;
            if (SPLIT) {
                const float sc = (col < 1024) ? 0.125f : 1.f;
                uint32_t h0, l0, h1, l1;
                split2(c[i][j][0] * sc, c[i][j][1] * sc, h0, l0);
                split2(c[i][j][2] * sc, c[i][j][3] * sc, h1, l1);
                *(uint32_t*)(outH + (size_t)row * NOUT + col) = h0;
                *(uint32_t*)(outL + (size_t)row * NOUT + col) = l0;
                *(uint32_t*)(outH + (size_t)(row + 8) * NOUT + col) = h1;
                *(uint32_t*)(outL + (size_t)(row + 8) * NOUT + col) = l1;
            } else {
                *(float2*)(outF + (size_t)row * NOUT + col) =
                    make_float2(c[i][j][0], c[i][j][1]);
                *(float2*)(outF + (size_t)(row + 8) * NOUT + col) =
                    make_float2(c[i][j][2], c[i][j][3]);
            }
        }
    }
}

// ---------------------------------------------------------------------------
// Flash attention (causal), fp16 compensated, register P, pass-ordered MMAs.
// ---------------------------------------------------------------------------
#define FA_SMEM 81920

__global__ void __launch_bounds__(128, 2)
flash16(const __half* __restrict__ qh, const __half* __restrict__ ql,
        float* __restrict__ out)
{
    extern __shared__ char smx[];
    const uint32_t smB = su32(smx);
    const int tid  = threadIdx.x;
    const int w    = tid >> 5;
    const int lane = tid & 31;
    const int lr   = lane & 7, g = lane >> 3;
    const int qr   = lane >> 2, qc = lane & 3;
    const int bhx  = blockIdx.y;
    const int b    = bhx >> 4;
    const int hh   = bhx & 15;
    const int m0   = blockIdx.x * 64;

    const size_t base = (size_t)b * T_ * 3072 + hh * 64;
    const __half* qhp = qh + base;
    const __half* qlp = ql + base;
    const __half* khp = qhp + 1024;
    const __half* klp = qlp + 1024;
    const __half* vhp = qhp + 2048;
    const __half* vlp = qlp + 2048;

    int sRow[4], sC[4];
    uint32_t sDst[4];
#pragma unroll
    for (int q = 0; q < 4; q++) {
        int id = tid * 4 + q;
        sRow[q] = id >> 3;
        sC[q]   = id & 7;
        sDst[q] = sRow[q] * 128 + ((sC[q] ^ (sRow[q] & 7)) << 4);
    }

    auto stage_kv = [&](int j0, int s) {
        const uint32_t bb = smB + 16384 + s * 32768;
#pragma unroll
        for (int q = 0; q < 4; q++) {
            const size_t so = (size_t)(j0 + sRow[q]) * 3072 + sC[q] * 8;
            cpa16(bb + sDst[q],         khp + so);
            cpa16(bb + 8192  + sDst[q], klp + so);
            cpa16(bb + 16384 + sDst[q], vhp + so);
            cpa16(bb + 24576 + sDst[q], vlp + so);
        }
        CP_COMMIT();
    };

#pragma unroll
    for (int q = 0; q < 4; q++) {
        const size_t so = (size_t)(m0 + sRow[q]) * 3072 + sC[q] * 8;
        cpa16(smB + sDst[q],        qhp + so);
        cpa16(smB + 8192 + sDst[q], qlp + so);
    }
    CP_COMMIT();
    stage_kv(0, 0);
    asm volatile("cp.async.wait_group 1;" ::: "memory");
    __syncthreads();

    const int aRow = lr + ((g & 1) << 3), aCh = g >> 1;
    const int kRow = lr + ((g >> 1) << 3), kCh = g & 1;
    uint32_t qfh[4][4], qfl[4][4];
#pragma unroll
    for (int kk = 0; kk < 4; kk++) {
        uint32_t a = smB + (w * 16 + aRow) * 128 + (((2 * kk + aCh) ^ lr) << 4);
        ldm4(qfh[kk], a);
        ldm4(qfl[kk], a + 8192);
    }

    float o_[8][4];
#pragma unroll
    for (int n = 0; n < 8; n++)
#pragma unroll
        for (int e = 0; e < 4; e++) o_[n][e] = 0.f;
    float m0v = -1e30f, m1v = -1e30f, l0v = 0.f, l1v = 0.f;
    const int row0 = m0 + w * 16 + qr;

    for (int j0 = 0; j0 <= m0; j0 += 64) {
        const int st = (j0 >> 6) & 1;
        if (j0 + 64 <= m0) {
            stage_kv(j0 + 64, st ^ 1);
            asm volatile("cp.async.wait_group 1;" ::: "memory");
        } else {
            asm volatile("cp.async.wait_group 0;" ::: "memory");
        }
        __syncthreads();
        const uint32_t KB = smB + 16384 + st * 32768;
        const uint32_t VB = KB + 16384;

        float s_[8][4];
#pragma unroll
        for (int n = 0; n < 8; n++)
#pragma unroll
            for (int e = 0; e < 4; e++) s_[n][e] = 0.f;

#pragma unroll
        for (int kk = 0; kk < 4; kk++) {
            uint32_t kh4[4][4], kl4[4][4];
#pragma unroll
            for (int np = 0; np < 4; np++) {
                uint32_t a = KB + np * 2048 + kRow * 128 +
                             (((2 * kk + kCh) ^ lr) << 4);
                ldm4(kh4[np], a);
                ldm4(kl4[np], a + 8192);
            }
#pragma unroll
            for (int np = 0; np < 4; np++) {
                mma16(s_[2 * np],     qfh[kk], kh4[np]);
                mma16(s_[2 * np + 1], qfh[kk], kh4[np] + 2);
            }
#pragma unroll
            for (int np = 0; np < 4; np++) {
                mma16(s_[2 * np],     qfh[kk], kl4[np]);
                mma16(s_[2 * np + 1], qfh[kk], kl4[np] + 2);
            }
#pragma unroll
            for (int np = 0; np < 4; np++) {
                mma16(s_[2 * np],     qfl[kk], kh4[np]);
                mma16(s_[2 * np + 1], qfl[kk], kh4[np] + 2);
            }
        }

        if (j0 == m0) {
#pragma unroll
            for (int n = 0; n < 8; n++) {
                const int key = j0 + n * 8 + 2 * qc;
                if (key     > row0)     s_[n][0] = -1e30f;
                if (key + 1 > row0)     s_[n][1] = -1e30f;
                if (key     > row0 + 8) s_[n][2] = -1e30f;
                if (key + 1 > row0 + 8) s_[n][3] = -1e30f;
            }
        }

        float mx0 = -1e30f, mx1 = -1e30f;
#pragma unroll
        for (int n = 0; n < 8; n++) {
            mx0 = fmaxf(mx0, fmaxf(s_[n][0], s_[n][1]));
            mx1 = fmaxf(mx1, fmaxf(s_[n][2], s_[n][3]));
        }
        mx0 = fmaxf(mx0, __shfl_xor_sync(0xffffffffu, mx0, 1));
        mx0 = fmaxf(mx0, __shfl_xor_sync(0xffffffffu, mx0, 2));
        mx1 = fmaxf(mx1, __shfl_xor_sync(0xffffffffu, mx1, 1));
        mx1 = fmaxf(mx1, __shfl_xor_sync(0xffffffffu, mx1, 2));
        const float mn0 = fmaxf(m0v, mx0);
        const float mn1 = fmaxf(m1v, mx1);
        const float c0 = __expf(m0v - mn0);
        const float c1 = __expf(m1v - mn1);
        m0v = mn0; m1v = mn1;
        l0v *= c0;  l1v *= c1;
#pragma unroll
        for (int n = 0; n < 8; n++) {
            o_[n][0] *= c0; o_[n][1] *= c0;
            o_[n][2] *= c1; o_[n][3] *= c1;
        }

        uint32_t pAh[8], pAl[8], pBh[8], pBl[8];
        float ps0 = 0.f, ps1 = 0.f;
#pragma unroll
        for (int n = 0; n < 8; n++) {
            float p0 = __expf(s_[n][0] - mn0);
            float p1 = __expf(s_[n][1] - mn0);
            float p2 = __expf(s_[n][2] - mn1);
            float p3 = __expf(s_[n][3] - mn1);
            ps0 += p0 + p1;
            ps1 += p2 + p3;
            split2(p0, p1, pAh[n], pAl[n]);
            split2(p2, p3, pBh[n], pBl[n]);
        }
        ps0 += __shfl_xor_sync(0xffffffffu, ps0, 1);
        ps0 += __shfl_xor_sync(0xffffffffu, ps0, 2);
        ps1 += __shfl_xor_sync(0xffffffffu, ps1, 1);
        ps1 += __shfl_xor_sync(0xffffffffu, ps1, 2);
        l0v += ps0; l1v += ps1;

#pragma unroll
        for (int kk = 0; kk < 4; kk++) {
            uint32_t ah4[4] = { pAh[2 * kk], pBh[2 * kk],
                                pAh[2 * kk + 1], pBh[2 * kk + 1] };
            uint32_t al4[4] = { pAl[2 * kk], pBl[2 * kk],
                                pAl[2 * kk + 1], pBl[2 * kk + 1] };
            uint32_t vh4[4][4], vl4[4][4];
#pragma unroll
            for (int np = 0; np < 4; np++) {
                uint32_t a = VB + kk * 2048 + aRow * 128 +
                             (((2 * np + aCh) ^ lr) << 4);
                ldm4t(vh4[np], a);
                ldm4t(vl4[np], a + 8192);
            }
#pragma unroll
            for (int np = 0; np < 4; np++) {
                mma16(o_[2 * np],     ah4, vh4[np]);
                mma16(o_[2 * np + 1], ah4, vh4[np] + 2);
            }
#pragma unroll
            for (int np = 0; np < 4; np++) {
                mma16(o_[2 * np],     ah4, vl4[np]);
                mma16(o_[2 * np + 1], ah4, vl4[np] + 2);
            }
#pragma unroll
            for (int np = 0; np < 4; np++) {
                mma16(o_[2 * np],     al4, vh4[np]);
                mma16(o_[2 * np + 1], al4, vh4[np] + 2);
            }
        }
        __syncthreads();
    }

    const float i0 = 1.f / l0v;
    const float i1 = 1.f / l1v;
    float* oP0 = out + ((size_t)b * T_ + row0) * C_ + hh * 64;
    float* oP1 = oP0 + 8 * C_;
#pragma unroll
    for (int n = 0; n < 8; n++) {
        *(float2*)(oP0 + n * 8 + 2 * qc) = make_float2(o_[n][0] * i0, o_[n][1] * i0);
        *(float2*)(oP1 + n * 8 + 2 * qc) = make_float2(o_[n][2] * i1, o_[n][3] * i1);
    }
}

// ---------------------------------------------------------------------------
// Depthwise causal conv (K=4) + bias + residual -> fp16 hi/lo
// ---------------------------------------------------------------------------
__global__ void __launch_bounds__(256)
conv_split(const float* __restrict__ x, const float* __restrict__ w,
           const float* __restrict__ bias, __half* __restrict__ yh,
           __half* __restrict__ yl)
{
    int i2 = blockIdx.x * blockDim.x + threadIdx.x;
    if (i2 >= MTOK * C_ / 2) return;
    const int idx = i2 * 2;
    const int c = idx & (C_ - 1);
    const int t = (idx >> 10) & (T_ - 1);

    float s0 = bias[c]     + x[idx];
    float s1 = bias[c + 1] + x[idx + 1];
#pragma unroll
    for (int k = 0; k < 4; k++) {
        int ts = t + k - 3;
        if (ts >= 0) {
            s0 += w[c * 4 + k]       * x[idx + (k - 3) * C_];
            s1 += w[(c + 1) * 4 + k] * x[idx + 1 + (k - 3) * C_];
        }
    }
    uint32_t h, l;
    split2(s0, s1, h, l);
    *(uint32_t*)(yh + idx) = h;
    *(uint32_t*)(yl + idx) = l;
}

// ---------------------------------------------------------------------------
// Launch
// ---------------------------------------------------------------------------
extern "C" void kernel_launch(void* const* d_in, const int* in_sizes, int n_in,
                              void* d_out, int out_size)
{
    const float* x     = (const float*)d_in[0];
    const float* Wqkv  = (const float*)d_in[1];
    const float* Wout  = (const float*)d_in[2];
    const float* convw = (const float*)d_in[3];
    const float* convb = (const float*)d_in[4];
    float* out = (float*)d_out;

    __half *xh, *xl, *wqh, *wql, *woh, *wol, *qh, *ql, *ch, *cl;
    float* attn;
    cudaGetSymbolAddress((void**)&xh,  g_xh);
    cudaGetSymbolAddress((void**)&xl,  g_xl);
    cudaGetSymbolAddress((void**)&wqh, g_wqh);
    cudaGetSymbolAddress((void**)&wql, g_wql);
    cudaGetSymbolAddress((void**)&woh, g_woh);
    cudaGetSymbolAddress((void**)&wol, g_wol);
    cudaGetSymbolAddress((void**)&qh,  g_qh);
    cudaGetSymbolAddress((void**)&ql,  g_ql);
    cudaGetSymbolAddress((void**)&ch,  g_ch);
    cudaGetSymbolAddress((void**)&cl,  g_cl);
    cudaGetSymbolAddress((void**)&attn, g_attn);

    cudaFuncSetAttribute(gemm16<3072, true>,
                         cudaFuncAttributeMaxDynamicSharedMemorySize, GSM);
    cudaFuncSetAttribute(gemm16<1024, false>,
                         cudaFuncAttributeMaxDynamicSharedMemorySize, GSM);
    cudaFuncSetAttribute(flash16,
                         cudaFuncAttributeMaxDynamicSharedMemorySize, FA_SMEM);

    // 0) split inputs
    split_pair<<<MTOK * C_ / 2 / 256, 256>>>((const float2*)x,
                                             (__half2*)xh, (__half2*)xl,
                                             MTOK * C_ / 2);
    split_pair<<<3 * C_ * C_ / 2 / 256, 256>>>((const float2*)Wqkv,
                                               (__half2*)wqh, (__half2*)wql,
                                               3 * C_ * C_ / 2);
    split_pair<<<C_ * C_ / 2 / 256, 256>>>((const float2*)Wout,
                                           (__half2*)woh, (__half2*)wol,
                                           C_ * C_ / 2);

    // 1) QKV projection (emits split hi/lo, Q pre-scaled)
    gemm16<3072, true><<<dim3(24, 64), 256, GSM>>>(xh, xl, wqh, wql,
                                                   nullptr, qh, ql);

    // 2) attention
    flash16<<<dim3(T_ / 64, B_ * H_), 128, FA_SMEM>>>(qh, ql, attn);

    // 3) conv + residual -> split
    conv_split<<<MTOK * C_ / 2 / 256, 256>>>(attn, convw, convb, ch, cl);

    // 4) output projection
    gemm16<1024, false><<<dim3(8, 64), 256, GSM>>>(ch, cl, woh, wol,
                                                   out, nullptr, nullptr);
}

// round 9
// speedup vs baseline: 3.0411x; 1.0243x over previous
#include <cuda_runtime.h>
#include <cuda_fp16.h>
#include <cstdint>
#include <cstddef>

#define B_   4
#define T_   2048
#define C_   1024
#define H_   16
#define MTOK 8192

// ---------------------------------------------------------------------------
// Scratch
// ---------------------------------------------------------------------------
__device__ __half g_xh[(size_t)MTOK * C_],     g_xl[(size_t)MTOK * C_];
__device__ __half g_wqh[(size_t)3 * C_ * C_],  g_wql[(size_t)3 * C_ * C_];
__device__ __half g_woh[(size_t)C_ * C_],      g_wol[(size_t)C_ * C_];
__device__ __half g_qh[(size_t)MTOK * 3 * C_], g_ql[(size_t)MTOK * 3 * C_];
__device__ __half g_ch[(size_t)MTOK * C_],     g_cl[(size_t)MTOK * C_];
__device__ float  g_attn[(size_t)MTOK * C_];

// ---------------------------------------------------------------------------
// Helpers
// ---------------------------------------------------------------------------
__device__ __forceinline__ uint32_t su32(const void* p) {
    uint32_t a;
    asm("{ .reg .u64 t; cvta.to.shared.u64 t, %1; cvt.u32.u64 %0, t; }"
        : "=r"(a) : "l"(p));
    return a;
}
__device__ __forceinline__ void cpa16(uint32_t dst, const void* src) {
    asm volatile("cp.async.cg.shared.global [%0], [%1], 16;" :: "r"(dst), "l"(src));
}
#define CP_COMMIT() asm volatile("cp.async.commit_group;" ::: "memory")

__device__ __forceinline__ void ldm4(uint32_t* r, uint32_t a) {
    asm volatile("ldmatrix.sync.aligned.m8n8.x4.shared.b16 {%0,%1,%2,%3}, [%4];"
                 : "=r"(r[0]), "=r"(r[1]), "=r"(r[2]), "=r"(r[3]) : "r"(a));
}
__device__ __forceinline__ void ldm4t(uint32_t* r, uint32_t a) {
    asm volatile("ldmatrix.sync.aligned.m8n8.x4.trans.shared.b16 {%0,%1,%2,%3}, [%4];"
                 : "=r"(r[0]), "=r"(r[1]), "=r"(r[2]), "=r"(r[3]) : "r"(a));
}
__device__ __forceinline__ void mma16(float* d, const uint32_t* a, const uint32_t* b) {
    asm volatile(
        "mma.sync.aligned.m16n8k16.row.col.f32.f16.f16.f32 "
        "{%0,%1,%2,%3}, {%4,%5,%6,%7}, {%8,%9}, {%0,%1,%2,%3};"
        : "+f"(d[0]), "+f"(d[1]), "+f"(d[2]), "+f"(d[3])
        : "r"(a[0]), "r"(a[1]), "r"(a[2]), "r"(a[3]), "r"(b[0]), "r"(b[1]));
}
__device__ __forceinline__ void split2(float x, float y, uint32_t& h, uint32_t& l) {
    __half2 hh = __float22half2_rn(make_float2(x, y));
    float rx = x - __half2float(__low2half(hh));
    float ry = y - __half2float(__high2half(hh));
    __half2 ll = __float22half2_rn(make_float2(rx, ry));
    h = *reinterpret_cast<uint32_t*>(&hh);
    l = *reinterpret_cast<uint32_t*>(&ll);
}

// ---------------------------------------------------------------------------
// fp32 -> fp16 hi/lo split
// ---------------------------------------------------------------------------
__global__ void __launch_bounds__(256)
split_pair(const float2* __restrict__ in, __half2* __restrict__ oh,
           __half2* __restrict__ ol, int n2)
{
    int i = blockIdx.x * blockDim.x + threadIdx.x;
    if (i >= n2) return;
    float2 v = in[i];
    uint32_t h, l;
    split2(v.x, v.y, h, l);
    oh[i] = *reinterpret_cast<__half2*>(&h);
    ol[i] = *reinterpret_cast<__half2*>(&l);
}

// ---------------------------------------------------------------------------
// fp16-compensated GEMM (NT): 128x128 tile, BK=32, 2 CTAs/SM.  (Round-8, good)
// ---------------------------------------------------------------------------
#define GSM 65536

template<int NOUT, bool SPLIT>
__global__ void __launch_bounds__(256, 2)
gemm16(const __half* __restrict__ Ah, const __half* __restrict__ Al,
       const __half* __restrict__ Bh, const __half* __restrict__ Bl,
       float* __restrict__ outF, __half* __restrict__ outH,
       __half* __restrict__ outL)
{
    extern __shared__ char smx[];
    const uint32_t smB = su32(smx);
    const int tid  = threadIdx.x;
    const int lane = tid & 31;
    const int wid  = tid >> 5;
    const int wm   = wid & 1;
    const int wn   = wid >> 1;
    const int lr   = lane & 7, g = lane >> 3;
    const int qr   = lane >> 2, qc = lane & 3;
    const int bm   = blockIdx.y * 128;
    const int bn   = blockIdx.x * 128;

    const int aCh = g >> 1;
    const int bCh = g & 1;
    const int aRowF = lr + ((g & 1) << 3);
    const int bRowF = lr + ((g >> 1) << 3);

    const int id0 = tid * 2, id1 = tid * 2 + 1;
    const int r0 = id0 >> 2, c0 = id0 & 3;
    const int r1 = id1 >> 2, c1 = id1 & 3;
    const uint32_t o0 = r0 * 64 + (((c0 ^ ((r0 >> 1) & 3))) << 4);
    const uint32_t o1 = r1 * 64 + (((c1 ^ ((r1 >> 1) & 3))) << 4);

    auto stage = [&](int k0, int s) {
        const uint32_t bb = smB + s * 32768;
        const size_t a0 = (size_t)(bm + r0) * 1024 + k0 + c0 * 8;
        const size_t a1 = (size_t)(bm + r1) * 1024 + k0 + c1 * 8;
        const size_t b0 = (size_t)(bn + r0) * 1024 + k0 + c0 * 8;
        const size_t b1 = (size_t)(bn + r1) * 1024 + k0 + c1 * 8;
        cpa16(bb + o0,         Ah + a0);  cpa16(bb + o1,         Ah + a1);
        cpa16(bb + 8192 + o0,  Al + a0);  cpa16(bb + 8192 + o1,  Al + a1);
        cpa16(bb + 16384 + o0, Bh + b0);  cpa16(bb + 16384 + o1, Bh + b1);
        cpa16(bb + 24576 + o0, Bl + b0);  cpa16(bb + 24576 + o1, Bl + b1);
        CP_COMMIT();
    };

    float c[4][4][4];
#pragma unroll
    for (int i = 0; i < 4; i++)
#pragma unroll
        for (int j = 0; j < 4; j++)
#pragma unroll
            for (int e = 0; e < 4; e++) c[i][j][e] = 0.f;

    stage(0, 0);

    for (int ki = 0; ki < 32; ki++) {
        if (ki < 31) {
            stage((ki + 1) * 32, (ki + 1) & 1);
            asm volatile("cp.async.wait_group 1;" ::: "memory");
        } else {
            asm volatile("cp.async.wait_group 0;" ::: "memory");
        }
        __syncthreads();
        const uint32_t st = smB + (ki & 1) * 32768;

#pragma unroll
        for (int kk = 0; kk < 2; kk++) {
            uint32_t af[4][4];
#pragma unroll
            for (int i = 0; i < 4; i++) {
                const int row = wm * 64 + i * 16 + aRowF;
                ldm4(af[i], st + row * 64 +
                     (((2 * kk + aCh) ^ ((row >> 1) & 3)) << 4));
            }
            uint32_t bh4[2][4], bl4[2][4];
#pragma unroll
            for (int jp = 0; jp < 2; jp++) {
                const int row = wn * 32 + jp * 16 + bRowF;
                const uint32_t a = st + 16384 + row * 64 +
                                   (((2 * kk + bCh) ^ ((row >> 1) & 3)) << 4);
                ldm4(bh4[jp], a);
                ldm4(bl4[jp], a + 8192);
            }
#pragma unroll
            for (int jp = 0; jp < 2; jp++)
#pragma unroll
                for (int i = 0; i < 4; i++) {
                    mma16(c[i][2 * jp],     af[i], bh4[jp]);
                    mma16(c[i][2 * jp + 1], af[i], bh4[jp] + 2);
                }
#pragma unroll
            for (int jp = 0; jp < 2; jp++)
#pragma unroll
                for (int i = 0; i < 4; i++) {
                    mma16(c[i][2 * jp],     af[i], bl4[jp]);
                    mma16(c[i][2 * jp + 1], af[i], bl4[jp] + 2);
                }
#pragma unroll
            for (int i = 0; i < 4; i++) {
                const int row = wm * 64 + i * 16 + aRowF;
                ldm4(af[i], st + 8192 + row * 64 +
                     (((2 * kk + aCh) ^ ((row >> 1) & 3)) << 4));
            }
#pragma unroll
            for (int jp = 0; jp < 2; jp++)
#pragma unroll
                for (int i = 0; i < 4; i++) {
                    mma16(c[i][2 * jp],     af[i], bh4[jp]);
                    mma16(c[i][2 * jp + 1], af[i], bh4[jp] + 2);
                }
        }
        __syncthreads();
    }

#pragma unroll
    for (int i = 0; i < 4; i++) {
#pragma unroll
        for (int j = 0; j < 4; j++) {
            const int row = bm + wm * 64 + i * 16 + qr;
            const int col = bn + wn * 32 + j * 8 + 2 * qc;
            if (SPLIT) {
                const float sc = (col < 1024) ? 0.125f : 1.f;
                uint32_t h0, l0, h1, l1;
                split2(c[i][j][0] * sc, c[i][j][1] * sc, h0, l0);
                split2(c[i][j][2] * sc, c[i][j][3] * sc, h1, l1);
                *(uint32_t*)(outH + (size_t)row * NOUT + col) = h0;
                *(uint32_t*)(outL + (size_t)row * NOUT + col) = l0;
                *(uint32_t*)(outH + (size_t)(row + 8) * NOUT + col) = h1;
                *(uint32_t*)(outL + (size_t)(row + 8) * NOUT + col) = l1;
            } else {
                *(float2*)(outF + (size_t)row * NOUT + col) =
                    make_float2(c[i][j][0], c[i][j][1]);
                *(float2*)(outF + (size_t)(row + 8) * NOUT + col) =
                    make_float2(c[i][j][2], c[i][j][3]);
            }
        }
    }
}

// ---------------------------------------------------------------------------
// Flash attention (causal), fp16 compensated. v2: 64KB smem (Q staging region
// recycled as KV stage 0 after fragment preload) -> 3 CTAs/SM.
// ---------------------------------------------------------------------------
#define FA_SMEM 65536

__global__ void __launch_bounds__(128, 3)
flash16(const __half* __restrict__ qh, const __half* __restrict__ ql,
        float* __restrict__ out)
{
    extern __shared__ char smx[];
    const uint32_t smB = su32(smx);
    const int tid  = threadIdx.x;
    const int w    = tid >> 5;
    const int lane = tid & 31;
    const int lr   = lane & 7, g = lane >> 3;
    const int qr   = lane >> 2, qc = lane & 3;
    const int bhx  = blockIdx.y;
    const int b    = bhx >> 4;
    const int hh   = bhx & 15;
    const int m0   = blockIdx.x * 64;

    const size_t base = (size_t)b * T_ * 3072 + hh * 64;
    const __half* qhp = qh + base;
    const __half* qlp = ql + base;
    const __half* khp = qhp + 1024;
    const __half* klp = qlp + 1024;
    const __half* vhp = qhp + 2048;
    const __half* vlp = qlp + 2048;

    int sRow[4], sC[4];
    uint32_t sDst[4];
#pragma unroll
    for (int q = 0; q < 4; q++) {
        int id = tid * 4 + q;
        sRow[q] = id >> 3;
        sC[q]   = id & 7;
        sDst[q] = sRow[q] * 128 + ((sC[q] ^ (sRow[q] & 7)) << 4);
    }

    // KV stage s lives at smB + s*32768: Kh|Kl|Vh|Vl (8KB each)
    auto stage_kv = [&](int j0, int s) {
        const uint32_t bb = smB + s * 32768;
#pragma unroll
        for (int q = 0; q < 4; q++) {
            const size_t so = (size_t)(j0 + sRow[q]) * 3072 + sC[q] * 8;
            cpa16(bb + sDst[q],         khp + so);
            cpa16(bb + 8192  + sDst[q], klp + so);
            cpa16(bb + 16384 + sDst[q], vhp + so);
            cpa16(bb + 24576 + sDst[q], vlp + so);
        }
        CP_COMMIT();
    };

    // stage Q into [smB, smB+16K) -- this region is recycled as KV stage 0
#pragma unroll
    for (int q = 0; q < 4; q++) {
        const size_t so = (size_t)(m0 + sRow[q]) * 3072 + sC[q] * 8;
        cpa16(smB + sDst[q],        qhp + so);
        cpa16(smB + 8192 + sDst[q], qlp + so);
    }
    CP_COMMIT();
    asm volatile("cp.async.wait_group 0;" ::: "memory");
    __syncthreads();

    const int aRow = lr + ((g & 1) << 3), aCh = g >> 1;
    const int kRow = lr + ((g >> 1) << 3), kCh = g & 1;
    uint32_t qfh[4][4], qfl[4][4];
#pragma unroll
    for (int kk = 0; kk < 4; kk++) {
        uint32_t a = smB + (w * 16 + aRow) * 128 + (((2 * kk + aCh) ^ lr) << 4);
        ldm4(qfh[kk], a);
        ldm4(qfl[kk], a + 8192);
    }
    __syncthreads();          // all Q fragment loads done before stage-0 overwrite
    stage_kv(0, 0);

    float o_[8][4];
#pragma unroll
    for (int n = 0; n < 8; n++)
#pragma unroll
        for (int e = 0; e < 4; e++) o_[n][e] = 0.f;
    float m0v = -1e30f, m1v = -1e30f, l0v = 0.f, l1v = 0.f;
    const int row0 = m0 + w * 16 + qr;

    for (int j0 = 0; j0 <= m0; j0 += 64) {
        const int st = (j0 >> 6) & 1;
        if (j0 + 64 <= m0) {
            stage_kv(j0 + 64, st ^ 1);
            asm volatile("cp.async.wait_group 1;" ::: "memory");
        } else {
            asm volatile("cp.async.wait_group 0;" ::: "memory");
        }
        __syncthreads();
        const uint32_t KB = smB + st * 32768;
        const uint32_t VB = KB + 16384;

        float s_[8][4];
#pragma unroll
        for (int n = 0; n < 8; n++)
#pragma unroll
            for (int e = 0; e < 4; e++) s_[n][e] = 0.f;

#pragma unroll
        for (int kk = 0; kk < 4; kk++) {
            uint32_t kh4[4][4], kl4[4][4];
#pragma unroll
            for (int np = 0; np < 4; np++) {
                uint32_t a = KB + np * 2048 + kRow * 128 +
                             (((2 * kk + kCh) ^ lr) << 4);
                ldm4(kh4[np], a);
                ldm4(kl4[np], a + 8192);
            }
#pragma unroll
            for (int np = 0; np < 4; np++) {
                mma16(s_[2 * np],     qfh[kk], kh4[np]);
                mma16(s_[2 * np + 1], qfh[kk], kh4[np] + 2);
            }
#pragma unroll
            for (int np = 0; np < 4; np++) {
                mma16(s_[2 * np],     qfh[kk], kl4[np]);
                mma16(s_[2 * np + 1], qfh[kk], kl4[np] + 2);
            }
#pragma unroll
            for (int np = 0; np < 4; np++) {
                mma16(s_[2 * np],     qfl[kk], kh4[np]);
                mma16(s_[2 * np + 1], qfl[kk], kh4[np] + 2);
            }
        }

        if (j0 == m0) {
#pragma unroll
            for (int n = 0; n < 8; n++) {
                const int key = j0 + n * 8 + 2 * qc;
                if (key     > row0)     s_[n][0] = -1e30f;
                if (key + 1 > row0)     s_[n][1] = -1e30f;
                if (key     > row0 + 8) s_[n][2] = -1e30f;
                if (key + 1 > row0 + 8) s_[n][3] = -1e30f;
            }
        }

        float mx0 = -1e30f, mx1 = -1e30f;
#pragma unroll
        for (int n = 0; n < 8; n++) {
            mx0 = fmaxf(mx0, fmaxf(s_[n][0], s_[n][1]));
            mx1 = fmaxf(mx1, fmaxf(s_[n][2], s_[n][3]));
        }
        mx0 = fmaxf(mx0, __shfl_xor_sync(0xffffffffu, mx0, 1));
        mx0 = fmaxf(mx0, __shfl_xor_sync(0xffffffffu, mx0, 2));
        mx1 = fmaxf(mx1, __shfl_xor_sync(0xffffffffu, mx1, 1));
        mx1 = fmaxf(mx1, __shfl_xor_sync(0xffffffffu, mx1, 2));
        const float mn0 = fmaxf(m0v, mx0);
        const float mn1 = fmaxf(m1v, mx1);
        const float c0 = __expf(m0v - mn0);
        const float c1 = __expf(m1v - mn1);
        m0v = mn0; m1v = mn1;
        l0v *= c0;  l1v *= c1;
#pragma unroll
        for (int n = 0; n < 8; n++) {
            o_[n][0] *= c0; o_[n][1] *= c0;
            o_[n][2] *= c1; o_[n][3] *= c1;
        }

        uint32_t pAh[8], pAl[8], pBh[8], pBl[8];
        float ps0 = 0.f, ps1 = 0.f;
#pragma unroll
        for (int n = 0; n < 8; n++) {
            float p0 = __expf(s_[n][0] - mn0);
            float p1 = __expf(s_[n][1] - mn0);
            float p2 = __expf(s_[n][2] - mn1);
            float p3 = __expf(s_[n][3] - mn1);
            ps0 += p0 + p1;
            ps1 += p2 + p3;
            split2(p0, p1, pAh[n], pAl[n]);
            split2(p2, p3, pBh[n], pBl[n]);
        }
        ps0 += __shfl_xor_sync(0xffffffffu, ps0, 1);
        ps0 += __shfl_xor_sync(0xffffffffu, ps0, 2);
        ps1 += __shfl_xor_sync(0xffffffffu, ps1, 1);
        ps1 += __shfl_xor_sync(0xffffffffu, ps1, 2);
        l0v += ps0; l1v += ps1;

#pragma unroll
        for (int kk = 0; kk < 4; kk++) {
            uint32_t ah4[4] = { pAh[2 * kk], pBh[2 * kk],
                                pAh[2 * kk + 1], pBh[2 * kk + 1] };
            uint32_t al4[4] = { pAl[2 * kk], pBl[2 * kk],
                                pAl[2 * kk + 1], pBl[2 * kk + 1] };
            uint32_t vh4[4][4], vl4[4][4];
#pragma unroll
            for (int np = 0; np < 4; np++) {
                uint32_t a = VB + kk * 2048 + aRow * 128 +
                             (((2 * np + aCh) ^ lr) << 4);
                ldm4t(vh4[np], a);
                ldm4t(vl4[np], a + 8192);
            }
#pragma unroll
            for (int np = 0; np < 4; np++) {
                mma16(o_[2 * np],     ah4, vh4[np]);
                mma16(o_[2 * np + 1], ah4, vh4[np] + 2);
            }
#pragma unroll
            for (int np = 0; np < 4; np++) {
                mma16(o_[2 * np],     ah4, vl4[np]);
                mma16(o_[2 * np + 1], ah4, vl4[np] + 2);
            }
#pragma unroll
            for (int np = 0; np < 4; np++) {
                mma16(o_[2 * np],     al4, vh4[np]);
                mma16(o_[2 * np + 1], al4, vh4[np] + 2);
            }
        }
        __syncthreads();
    }

    const float i0 = 1.f / l0v;
    const float i1 = 1.f / l1v;
    float* oP0 = out + ((size_t)b * T_ + row0) * C_ + hh * 64;
    float* oP1 = oP0 + 8 * C_;
#pragma unroll
    for (int n = 0; n < 8; n++) {
        *(float2*)(oP0 + n * 8 + 2 * qc) = make_float2(o_[n][0] * i0, o_[n][1] * i0);
        *(float2*)(oP1 + n * 8 + 2 * qc) = make_float2(o_[n][2] * i1, o_[n][3] * i1);
    }
}

// ---------------------------------------------------------------------------
// Depthwise causal conv (K=4) + bias + residual -> fp16 hi/lo
// ---------------------------------------------------------------------------
__global__ void __launch_bounds__(256)
conv_split(const float* __restrict__ x, const float* __restrict__ w,
           const float* __restrict__ bias, __half* __restrict__ yh,
           __half* __restrict__ yl)
{
    int i2 = blockIdx.x * blockDim.x + threadIdx.x;
    if (i2 >= MTOK * C_ / 2) return;
    const int idx = i2 * 2;
    const int c = idx & (C_ - 1);
    const int t = (idx >> 10) & (T_ - 1);

    float s0 = bias[c]     + x[idx];
    float s1 = bias[c + 1] + x[idx + 1];
#pragma unroll
    for (int k = 0; k < 4; k++) {
        int ts = t + k - 3;
        if (ts >= 0) {
            s0 += w[c * 4 + k]       * x[idx + (k - 3) * C_];
            s1 += w[(c + 1) * 4 + k] * x[idx + 1 + (k - 3) * C_];
        }
    }
    uint32_t h, l;
    split2(s0, s1, h, l);
    *(uint32_t*)(yh + idx) = h;
    *(uint32_t*)(yl + idx) = l;
}

// ---------------------------------------------------------------------------
// Launch
// ---------------------------------------------------------------------------
extern "C" void kernel_launch(void* const* d_in, const int* in_sizes, int n_in,
                              void* d_out, int out_size)
{
    const float* x     = (const float*)d_in[0];
    const float* Wqkv  = (const float*)d_in[1];
    const float* Wout  = (const float*)d_in[2];
    const float* convw = (const float*)d_in[3];
    const float* convb = (const float*)d_in[4];
    float* out = (float*)d_out;

    __half *xh, *xl, *wqh, *wql, *woh, *wol, *qh, *ql, *ch, *cl;
    float* attn;
    cudaGetSymbolAddress((void**)&xh,  g_xh);
    cudaGetSymbolAddress((void**)&xl,  g_xl);
    cudaGetSymbolAddress((void**)&wqh, g_wqh);
    cudaGetSymbolAddress((void**)&wql, g_wql);
    cudaGetSymbolAddress((void**)&woh, g_woh);
    cudaGetSymbolAddress((void**)&wol, g_wol);
    cudaGetSymbolAddress((void**)&qh,  g_qh);
    cudaGetSymbolAddress((void**)&ql,  g_ql);
    cudaGetSymbolAddress((void**)&ch,  g_ch);
    cudaGetSymbolAddress((void**)&cl,  g_cl);
    cudaGetSymbolAddress((void**)&attn, g_attn);

    cudaFuncSetAttribute(gemm16<3072, true>,
                         cudaFuncAttributeMaxDynamicSharedMemorySize, GSM);
    cudaFuncSetAttribute(gemm16<1024, false>,
                         cudaFuncAttributeMaxDynamicSharedMemorySize, GSM);
    cudaFuncSetAttribute(flash16,
                         cudaFuncAttributeMaxDynamicSharedMemorySize, FA_SMEM);

    // 0) split inputs
    split_pair<<<MTOK * C_ / 2 / 256, 256>>>((const float2*)x,
                                             (__half2*)xh, (__half2*)xl,
                                             MTOK * C_ / 2);
    split_pair<<<3 * C_ * C_ / 2 / 256, 256>>>((const float2*)Wqkv,
                                               (__half2*)wqh, (__half2*)wql,
                                               3 * C_ * C_ / 2);
    split_pair<<<C_ * C_ / 2 / 256, 256>>>((const float2*)Wout,
                                           (__half2*)woh, (__half2*)wol,
                                           C_ * C_ / 2);

    // 1) QKV projection (emits split hi/lo, Q pre-scaled)
    gemm16<3072, true><<<dim3(24, 64), 256, GSM>>>(xh, xl, wqh, wql,
                                                   nullptr, qh, ql);

    // 2) attention
    flash16<<<dim3(T_ / 64, B_ * H_), 128, FA_SMEM>>>(qh, ql, attn);

    // 3) conv + residual -> split
    conv_split<<<MTOK * C_ / 2 / 256, 256>>>(attn, convw, convb, ch, cl);

    // 4) output projection
    gemm16<1024, false><<<dim3(8, 64), 256, GSM>>>(ch, cl, woh, wol,
                                                   out, nullptr, nullptr);
}

// round 10
// speedup vs baseline: 3.0698x; 1.0094x over previous
#include <cuda_runtime.h>
#include <cuda_fp16.h>
#include <cstdint>
#include <cstddef>

#define B_   4
#define T_   2048
#define C_   1024
#define H_   16
#define MTOK 8192

// ---------------------------------------------------------------------------
// Scratch
// ---------------------------------------------------------------------------
__device__ __half g_xh[(size_t)MTOK * C_],     g_xl[(size_t)MTOK * C_];
__device__ __half g_wqh[(size_t)3 * C_ * C_],  g_wql[(size_t)3 * C_ * C_];
__device__ __half g_woh[(size_t)C_ * C_],      g_wol[(size_t)C_ * C_];
__device__ __half g_qh[(size_t)MTOK * 3 * C_], g_ql[(size_t)MTOK * 3 * C_];
__device__ __half g_ch[(size_t)MTOK * C_],     g_cl[(size_t)MTOK * C_];
__device__ float  g_attn[(size_t)MTOK * C_];

// ---------------------------------------------------------------------------
// Helpers
// ---------------------------------------------------------------------------
__device__ __forceinline__ uint32_t su32(const void* p) {
    uint32_t a;
    asm("{ .reg .u64 t; cvta.to.shared.u64 t, %1; cvt.u32.u64 %0, t; }"
        : "=r"(a) : "l"(p));
    return a;
}
__device__ __forceinline__ void cpa16(uint32_t dst, const void* src) {
    asm volatile("cp.async.cg.shared.global [%0], [%1], 16;" :: "r"(dst), "l"(src));
}
#define CP_COMMIT() asm volatile("cp.async.commit_group;" ::: "memory")

__device__ __forceinline__ void ldm4(uint32_t* r, uint32_t a) {
    asm volatile("ldmatrix.sync.aligned.m8n8.x4.shared.b16 {%0,%1,%2,%3}, [%4];"
                 : "=r"(r[0]), "=r"(r[1]), "=r"(r[2]), "=r"(r[3]) : "r"(a));
}
__device__ __forceinline__ void ldm4t(uint32_t* r, uint32_t a) {
    asm volatile("ldmatrix.sync.aligned.m8n8.x4.trans.shared.b16 {%0,%1,%2,%3}, [%4];"
                 : "=r"(r[0]), "=r"(r[1]), "=r"(r[2]), "=r"(r[3]) : "r"(a));
}
__device__ __forceinline__ void mma16(float* d, const uint32_t* a, const uint32_t* b) {
    asm volatile(
        "mma.sync.aligned.m16n8k16.row.col.f32.f16.f16.f32 "
        "{%0,%1,%2,%3}, {%4,%5,%6,%7}, {%8,%9}, {%0,%1,%2,%3};"
        : "+f"(d[0]), "+f"(d[1]), "+f"(d[2]), "+f"(d[3])
        : "r"(a[0]), "r"(a[1]), "r"(a[2]), "r"(a[3]), "r"(b[0]), "r"(b[1]));
}
__device__ __forceinline__ void split2(float x, float y, uint32_t& h, uint32_t& l) {
    __half2 hh = __float22half2_rn(make_float2(x, y));
    float rx = x - __half2float(__low2half(hh));
    float ry = y - __half2float(__high2half(hh));
    __half2 ll = __float22half2_rn(make_float2(rx, ry));
    h = *reinterpret_cast<uint32_t*>(&hh);
    l = *reinterpret_cast<uint32_t*>(&ll);
}

// ---------------------------------------------------------------------------
// fp32 -> fp16 hi/lo split
// ---------------------------------------------------------------------------
__global__ void __launch_bounds__(256)
split_pair(const float2* __restrict__ in, __half2* __restrict__ oh,
           __half2* __restrict__ ol, int n2)
{
    int i = blockIdx.x * blockDim.x + threadIdx.x;
    if (i >= n2) return;
    float2 v = in[i];
    uint32_t h, l;
    split2(v.x, v.y, h, l);
    oh[i] = *reinterpret_cast<__half2*>(&h);
    ol[i] = *reinterpret_cast<__half2*>(&l);
}

// ---------------------------------------------------------------------------
// fp16-compensated GEMM v3 (NT): 128x128 tile, BK=32, 3-stage cp.async
// pipeline with ONE __syncthreads per K-chunk, 2 CTAs/SM (96KB smem).
// ---------------------------------------------------------------------------
#define GSM 98304

template<int NOUT, bool SPLIT>
__global__ void __launch_bounds__(256, 2)
gemm16(const __half* __restrict__ Ah, const __half* __restrict__ Al,
       const __half* __restrict__ Bh, const __half* __restrict__ Bl,
       float* __restrict__ outF, __half* __restrict__ outH,
       __half* __restrict__ outL)
{
    extern __shared__ char smx[];
    const uint32_t smB = su32(smx);
    const int tid  = threadIdx.x;
    const int lane = tid & 31;
    const int wid  = tid >> 5;
    const int wm   = wid & 1;
    const int wn   = wid >> 1;
    const int lr   = lane & 7, g = lane >> 3;
    const int qr   = lane >> 2, qc = lane & 3;
    const int bm   = blockIdx.y * 128;
    const int bn   = blockIdx.x * 128;

    const int aCh = g >> 1;
    const int bCh = g & 1;
    const int aRowF = lr + ((g & 1) << 3);
    const int bRowF = lr + ((g >> 1) << 3);

    const int id0 = tid * 2, id1 = tid * 2 + 1;
    const int r0 = id0 >> 2, c0 = id0 & 3;
    const int r1 = id1 >> 2, c1 = id1 & 3;
    const uint32_t o0 = r0 * 64 + (((c0 ^ ((r0 >> 1) & 3))) << 4);
    const uint32_t o1 = r1 * 64 + (((c1 ^ ((r1 >> 1) & 3))) << 4);

    auto stage = [&](int k0, int s) {
        const uint32_t bb = smB + s * 32768;
        const size_t a0 = (size_t)(bm + r0) * 1024 + k0 + c0 * 8;
        const size_t a1 = (size_t)(bm + r1) * 1024 + k0 + c1 * 8;
        const size_t b0 = (size_t)(bn + r0) * 1024 + k0 + c0 * 8;
        const size_t b1 = (size_t)(bn + r1) * 1024 + k0 + c1 * 8;
        cpa16(bb + o0,         Ah + a0);  cpa16(bb + o1,         Ah + a1);
        cpa16(bb + 8192 + o0,  Al + a0);  cpa16(bb + 8192 + o1,  Al + a1);
        cpa16(bb + 16384 + o0, Bh + b0);  cpa16(bb + 16384 + o1, Bh + b1);
        cpa16(bb + 24576 + o0, Bl + b0);  cpa16(bb + 24576 + o1, Bl + b1);
        CP_COMMIT();
    };

    float c[4][4][4];
#pragma unroll
    for (int i = 0; i < 4; i++)
#pragma unroll
        for (int j = 0; j < 4; j++)
#pragma unroll
            for (int e = 0; e < 4; e++) c[i][j][e] = 0.f;

    // prologue: 2-deep prefetch
    stage(0, 0);
    stage(32, 1);

    for (int ki = 0; ki < 32; ki++) {
        // stage ki resident (allow stage ki+1 in flight)
        if (ki < 31) asm volatile("cp.async.wait_group 1;" ::: "memory");
        else         asm volatile("cp.async.wait_group 0;" ::: "memory");
        // all warps finished reading stage (ki+2)%3 (their iter ki-1 compute)
        __syncthreads();
        if (ki + 2 < 32) stage((ki + 2) * 32, (ki + 2) % 3);

        const uint32_t st = smB + (ki % 3) * 32768;

#pragma unroll
        for (int kk = 0; kk < 2; kk++) {
            uint32_t af[4][4];
#pragma unroll
            for (int i = 0; i < 4; i++) {
                const int row = wm * 64 + i * 16 + aRowF;
                ldm4(af[i], st + row * 64 +
                     (((2 * kk + aCh) ^ ((row >> 1) & 3)) << 4));
            }
            uint32_t bh4[2][4], bl4[2][4];
#pragma unroll
            for (int jp = 0; jp < 2; jp++) {
                const int row = wn * 32 + jp * 16 + bRowF;
                const uint32_t a = st + 16384 + row * 64 +
                                   (((2 * kk + bCh) ^ ((row >> 1) & 3)) << 4);
                ldm4(bh4[jp], a);
                ldm4(bl4[jp], a + 8192);
            }
#pragma unroll
            for (int jp = 0; jp < 2; jp++)
#pragma unroll
                for (int i = 0; i < 4; i++) {
                    mma16(c[i][2 * jp],     af[i], bh4[jp]);
                    mma16(c[i][2 * jp + 1], af[i], bh4[jp] + 2);
                }
#pragma unroll
            for (int jp = 0; jp < 2; jp++)
#pragma unroll
                for (int i = 0; i < 4; i++) {
                    mma16(c[i][2 * jp],     af[i], bl4[jp]);
                    mma16(c[i][2 * jp + 1], af[i], bl4[jp] + 2);
                }
#pragma unroll
            for (int i = 0; i < 4; i++) {
                const int row = wm * 64 + i * 16 + aRowF;
                ldm4(af[i], st + 8192 + row * 64 +
                     (((2 * kk + aCh) ^ ((row >> 1) & 3)) << 4));
            }
#pragma unroll
            for (int jp = 0; jp < 2; jp++)
#pragma unroll
                for (int i = 0; i < 4; i++) {
                    mma16(c[i][2 * jp],     af[i], bh4[jp]);
                    mma16(c[i][2 * jp + 1], af[i], bh4[jp] + 2);
                }
        }
    }

#pragma unroll
    for (int i = 0; i < 4; i++) {
#pragma unroll
        for (int j = 0; j < 4; j++) {
            const int row = bm + wm * 64 + i * 16 + qr;
            const int col = bn + wn * 32 + j * 8 + 2 * qc;
            if (SPLIT) {
                const float sc = (col < 1024) ? 0.125f : 1.f;
                uint32_t h0, l0, h1, l1;
                split2(c[i][j][0] * sc, c[i][j][1] * sc, h0, l0);
                split2(c[i][j][2] * sc, c[i][j][3] * sc, h1, l1);
                *(uint32_t*)(outH + (size_t)row * NOUT + col) = h0;
                *(uint32_t*)(outL + (size_t)row * NOUT + col) = l0;
                *(uint32_t*)(outH + (size_t)(row + 8) * NOUT + col) = h1;
                *(uint32_t*)(outL + (size_t)(row + 8) * NOUT + col) = l1;
            } else {
                *(float2*)(outF + (size_t)row * NOUT + col) =
                    make_float2(c[i][j][0], c[i][j][1]);
                *(float2*)(outF + (size_t)(row + 8) * NOUT + col) =
                    make_float2(c[i][j][2], c[i][j][3]);
            }
        }
    }
}

// ---------------------------------------------------------------------------
// Flash attention (causal), fp16 compensated, 64KB smem, 3 CTAs/SM.
// (Round-9 version, unchanged)
// ---------------------------------------------------------------------------
#define FA_SMEM 65536

__global__ void __launch_bounds__(128, 3)
flash16(const __half* __restrict__ qh, const __half* __restrict__ ql,
        float* __restrict__ out)
{
    extern __shared__ char smx[];
    const uint32_t smB = su32(smx);
    const int tid  = threadIdx.x;
    const int w    = tid >> 5;
    const int lane = tid & 31;
    const int lr   = lane & 7, g = lane >> 3;
    const int qr   = lane >> 2, qc = lane & 3;
    const int bhx  = blockIdx.y;
    const int b    = bhx >> 4;
    const int hh   = bhx & 15;
    const int m0   = blockIdx.x * 64;

    const size_t base = (size_t)b * T_ * 3072 + hh * 64;
    const __half* qhp = qh + base;
    const __half* qlp = ql + base;
    const __half* khp = qhp + 1024;
    const __half* klp = qlp + 1024;
    const __half* vhp = qhp + 2048;
    const __half* vlp = qlp + 2048;

    int sRow[4], sC[4];
    uint32_t sDst[4];
#pragma unroll
    for (int q = 0; q < 4; q++) {
        int id = tid * 4 + q;
        sRow[q] = id >> 3;
        sC[q]   = id & 7;
        sDst[q] = sRow[q] * 128 + ((sC[q] ^ (sRow[q] & 7)) << 4);
    }

    auto stage_kv = [&](int j0, int s) {
        const uint32_t bb = smB + s * 32768;
#pragma unroll
        for (int q = 0; q < 4; q++) {
            const size_t so = (size_t)(j0 + sRow[q]) * 3072 + sC[q] * 8;
            cpa16(bb + sDst[q],         khp + so);
            cpa16(bb + 8192  + sDst[q], klp + so);
            cpa16(bb + 16384 + sDst[q], vhp + so);
            cpa16(bb + 24576 + sDst[q], vlp + so);
        }
        CP_COMMIT();
    };

#pragma unroll
    for (int q = 0; q < 4; q++) {
        const size_t so = (size_t)(m0 + sRow[q]) * 3072 + sC[q] * 8;
        cpa16(smB + sDst[q],        qhp + so);
        cpa16(smB + 8192 + sDst[q], qlp + so);
    }
    CP_COMMIT();
    asm volatile("cp.async.wait_group 0;" ::: "memory");
    __syncthreads();

    const int aRow = lr + ((g & 1) << 3), aCh = g >> 1;
    const int kRow = lr + ((g >> 1) << 3), kCh = g & 1;
    uint32_t qfh[4][4], qfl[4][4];
#pragma unroll
    for (int kk = 0; kk < 4; kk++) {
        uint32_t a = smB + (w * 16 + aRow) * 128 + (((2 * kk + aCh) ^ lr) << 4);
        ldm4(qfh[kk], a);
        ldm4(qfl[kk], a + 8192);
    }
    __syncthreads();
    stage_kv(0, 0);

    float o_[8][4];
#pragma unroll
    for (int n = 0; n < 8; n++)
#pragma unroll
        for (int e = 0; e < 4; e++) o_[n][e] = 0.f;
    float m0v = -1e30f, m1v = -1e30f, l0v = 0.f, l1v = 0.f;
    const int row0 = m0 + w * 16 + qr;

    for (int j0 = 0; j0 <= m0; j0 += 64) {
        const int st = (j0 >> 6) & 1;
        if (j0 + 64 <= m0) {
            stage_kv(j0 + 64, st ^ 1);
            asm volatile("cp.async.wait_group 1;" ::: "memory");
        } else {
            asm volatile("cp.async.wait_group 0;" ::: "memory");
        }
        __syncthreads();
        const uint32_t KB = smB + st * 32768;
        const uint32_t VB = KB + 16384;

        float s_[8][4];
#pragma unroll
        for (int n = 0; n < 8; n++)
#pragma unroll
            for (int e = 0; e < 4; e++) s_[n][e] = 0.f;

#pragma unroll
        for (int kk = 0; kk < 4; kk++) {
            uint32_t kh4[4][4], kl4[4][4];
#pragma unroll
            for (int np = 0; np < 4; np++) {
                uint32_t a = KB + np * 2048 + kRow * 128 +
                             (((2 * kk + kCh) ^ lr) << 4);
                ldm4(kh4[np], a);
                ldm4(kl4[np], a + 8192);
            }
#pragma unroll
            for (int np = 0; np < 4; np++) {
                mma16(s_[2 * np],     qfh[kk], kh4[np]);
                mma16(s_[2 * np + 1], qfh[kk], kh4[np] + 2);
            }
#pragma unroll
            for (int np = 0; np < 4; np++) {
                mma16(s_[2 * np],     qfh[kk], kl4[np]);
                mma16(s_[2 * np + 1], qfh[kk], kl4[np] + 2);
            }
#pragma unroll
            for (int np = 0; np < 4; np++) {
                mma16(s_[2 * np],     qfl[kk], kh4[np]);
                mma16(s_[2 * np + 1], qfl[kk], kh4[np] + 2);
            }
        }

        if (j0 == m0) {
#pragma unroll
            for (int n = 0; n < 8; n++) {
                const int key = j0 + n * 8 + 2 * qc;
                if (key     > row0)     s_[n][0] = -1e30f;
                if (key + 1 > row0)     s_[n][1] = -1e30f;
                if (key     > row0 + 8) s_[n][2] = -1e30f;
                if (key + 1 > row0 + 8) s_[n][3] = -1e30f;
            }
        }

        float mx0 = -1e30f, mx1 = -1e30f;
#pragma unroll
        for (int n = 0; n < 8; n++) {
            mx0 = fmaxf(mx0, fmaxf(s_[n][0], s_[n][1]));
            mx1 = fmaxf(mx1, fmaxf(s_[n][2], s_[n][3]));
        }
        mx0 = fmaxf(mx0, __shfl_xor_sync(0xffffffffu, mx0, 1));
        mx0 = fmaxf(mx0, __shfl_xor_sync(0xffffffffu, mx0, 2));
        mx1 = fmaxf(mx1, __shfl_xor_sync(0xffffffffu, mx1, 1));
        mx1 = fmaxf(mx1, __shfl_xor_sync(0xffffffffu, mx1, 2));
        const float mn0 = fmaxf(m0v, mx0);
        const float mn1 = fmaxf(m1v, mx1);
        const float c0 = __expf(m0v - mn0);
        const float c1 = __expf(m1v - mn1);
        m0v = mn0; m1v = mn1;
        l0v *= c0;  l1v *= c1;
#pragma unroll
        for (int n = 0; n < 8; n++) {
            o_[n][0] *= c0; o_[n][1] *= c0;
            o_[n][2] *= c1; o_[n][3] *= c1;
        }

        uint32_t pAh[8], pAl[8], pBh[8], pBl[8];
        float ps0 = 0.f, ps1 = 0.f;
#pragma unroll
        for (int n = 0; n < 8; n++) {
            float p0 = __expf(s_[n][0] - mn0);
            float p1 = __expf(s_[n][1] - mn0);
            float p2 = __expf(s_[n][2] - mn1);
            float p3 = __expf(s_[n][3] - mn1);
            ps0 += p0 + p1;
            ps1 += p2 + p3;
            split2(p0, p1, pAh[n], pAl[n]);
            split2(p2, p3, pBh[n], pBl[n]);
        }
        ps0 += __shfl_xor_sync(0xffffffffu, ps0, 1);
        ps0 += __shfl_xor_sync(0xffffffffu, ps0, 2);
        ps1 += __shfl_xor_sync(0xffffffffu, ps1, 1);
        ps1 += __shfl_xor_sync(0xffffffffu, ps1, 2);
        l0v += ps0; l1v += ps1;

#pragma unroll
        for (int kk = 0; kk < 4; kk++) {
            uint32_t ah4[4] = { pAh[2 * kk], pBh[2 * kk],
                                pAh[2 * kk + 1], pBh[2 * kk + 1] };
            uint32_t al4[4] = { pAl[2 * kk], pBl[2 * kk],
                                pAl[2 * kk + 1], pBl[2 * kk + 1] };
            uint32_t vh4[4][4], vl4[4][4];
#pragma unroll
            for (int np = 0; np < 4; np++) {
                uint32_t a = VB + kk * 2048 + aRow * 128 +
                             (((2 * np + aCh) ^ lr) << 4);
                ldm4t(vh4[np], a);
                ldm4t(vl4[np], a + 8192);
            }
#pragma unroll
            for (int np = 0; np < 4; np++) {
                mma16(o_[2 * np],     ah4, vh4[np]);
                mma16(o_[2 * np + 1], ah4, vh4[np] + 2);
            }
#pragma unroll
            for (int np = 0; np < 4; np++) {
                mma16(o_[2 * np],     ah4, vl4[np]);
                mma16(o_[2 * np + 1], ah4, vl4[np] + 2);
            }
#pragma unroll
            for (int np = 0; np < 4; np++) {
                mma16(o_[2 * np],     al4, vh4[np]);
                mma16(o_[2 * np + 1], al4, vh4[np] + 2);
            }
        }
        __syncthreads();
    }

    const float i0 = 1.f / l0v;
    const float i1 = 1.f / l1v;
    float* oP0 = out + ((size_t)b * T_ + row0) * C_ + hh * 64;
    float* oP1 = oP0 + 8 * C_;
#pragma unroll
    for (int n = 0; n < 8; n++) {
        *(float2*)(oP0 + n * 8 + 2 * qc) = make_float2(o_[n][0] * i0, o_[n][1] * i0);
        *(float2*)(oP1 + n * 8 + 2 * qc) = make_float2(o_[n][2] * i1, o_[n][3] * i1);
    }
}

// ---------------------------------------------------------------------------
// Depthwise causal conv (K=4) + bias + residual -> fp16 hi/lo
// ---------------------------------------------------------------------------
__global__ void __launch_bounds__(256)
conv_split(const float* __restrict__ x, const float* __restrict__ w,
           const float* __restrict__ bias, __half* __restrict__ yh,
           __half* __restrict__ yl)
{
    int i2 = blockIdx.x * blockDim.x + threadIdx.x;
    if (i2 >= MTOK * C_ / 2) return;
    const int idx = i2 * 2;
    const int c = idx & (C_ - 1);
    const int t = (idx >> 10) & (T_ - 1);

    float s0 = bias[c]     + x[idx];
    float s1 = bias[c + 1] + x[idx + 1];
#pragma unroll
    for (int k = 0; k < 4; k++) {
        int ts = t + k - 3;
        if (ts >= 0) {
            s0 += w[c * 4 + k]       * x[idx + (k - 3) * C_];
            s1 += w[(c + 1) * 4 + k] * x[idx + 1 + (k - 3) * C_];
        }
    }
    uint32_t h, l;
    split2(s0, s1, h, l);
    *(uint32_t*)(yh + idx) = h;
    *(uint32_t*)(yl + idx) = l;
}

// ---------------------------------------------------------------------------
// Launch
// ---------------------------------------------------------------------------
extern "C" void kernel_launch(void* const* d_in, const int* in_sizes, int n_in,
                              void* d_out, int out_size)
{
    const float* x     = (const float*)d_in[0];
    const float* Wqkv  = (const float*)d_in[1];
    const float* Wout  = (const float*)d_in[2];
    const float* convw = (const float*)d_in[3];
    const float* convb = (const float*)d_in[4];
    float* out = (float*)d_out;

    __half *xh, *xl, *wqh, *wql, *woh, *wol, *qh, *ql, *ch, *cl;
    float* attn;
    cudaGetSymbolAddress((void**)&xh,  g_xh);
    cudaGetSymbolAddress((void**)&xl,  g_xl);
    cudaGetSymbolAddress((void**)&wqh, g_wqh);
    cudaGetSymbolAddress((void**)&wql, g_wql);
    cudaGetSymbolAddress((void**)&woh, g_woh);
    cudaGetSymbolAddress((void**)&wol, g_wol);
    cudaGetSymbolAddress((void**)&qh,  g_qh);
    cudaGetSymbolAddress((void**)&ql,  g_ql);
    cudaGetSymbolAddress((void**)&ch,  g_ch);
    cudaGetSymbolAddress((void**)&cl,  g_cl);
    cudaGetSymbolAddress((void**)&attn, g_attn);

    cudaFuncSetAttribute(gemm16<3072, true>,
                         cudaFuncAttributeMaxDynamicSharedMemorySize, GSM);
    cudaFuncSetAttribute(gemm16<1024, false>,
                         cudaFuncAttributeMaxDynamicSharedMemorySize, GSM);
    cudaFuncSetAttribute(flash16,
                         cudaFuncAttributeMaxDynamicSharedMemorySize, FA_SMEM);

    // 0) split inputs
    split_pair<<<MTOK * C_ / 2 / 256, 256>>>((const float2*)x,
                                             (__half2*)xh, (__half2*)xl,
                                             MTOK * C_ / 2);
    split_pair<<<3 * C_ * C_ / 2 / 256, 256>>>((const float2*)Wqkv,
                                               (__half2*)wqh, (__half2*)wql,
                                               3 * C_ * C_ / 2);
    split_pair<<<C_ * C_ / 2 / 256, 256>>>((const float2*)Wout,
                                           (__half2*)woh, (__half2*)wol,
                                           C_ * C_ / 2);

    // 1) QKV projection (emits split hi/lo, Q pre-scaled)
    gemm16<3072, true><<<dim3(24, 64), 256, GSM>>>(xh, xl, wqh, wql,
                                                   nullptr, qh, ql);

    // 2) attention
    flash16<<<dim3(T_ / 64, B_ * H_), 128, FA_SMEM>>>(qh, ql, attn);

    // 3) conv + residual -> split
    conv_split<<<MTOK * C_ / 2 / 256, 256>>>(attn, convw, convb, ch, cl);

    // 4) output projection
    gemm16<1024, false><<<dim3(8, 64), 256, GSM>>>(ch, cl, woh, wol,
                                                   out, nullptr, nullptr);
}

// round 11
// speedup vs baseline: 3.4173x; 1.1132x over previous
#include <cuda_runtime.h>
#include <cuda_fp16.h>
#include <cstdint>
#include <cstddef>

#define B_   4
#define T_   2048
#define C_   1024
#define H_   16
#define MTOK 8192
// Q scale folded with log2(e) for exp2-domain softmax
#define QSCALE 0.18033688011112042f

// ---------------------------------------------------------------------------
// Scratch
// ---------------------------------------------------------------------------
__device__ __half g_xh[(size_t)MTOK * C_],     g_xl[(size_t)MTOK * C_];
__device__ __half g_wqh[(size_t)3 * C_ * C_],  g_wql[(size_t)3 * C_ * C_];
__device__ __half g_woh[(size_t)C_ * C_],      g_wol[(size_t)C_ * C_];
__device__ __half g_qh[(size_t)MTOK * 3 * C_], g_ql[(size_t)MTOK * 3 * C_];
__device__ __half g_ch[(size_t)MTOK * C_],     g_cl[(size_t)MTOK * C_];
__device__ float  g_attn[(size_t)MTOK * C_];

// ---------------------------------------------------------------------------
// Helpers
// ---------------------------------------------------------------------------
__device__ __forceinline__ uint32_t su32(const void* p) {
    uint32_t a;
    asm("{ .reg .u64 t; cvta.to.shared.u64 t, %1; cvt.u32.u64 %0, t; }"
        : "=r"(a) : "l"(p));
    return a;
}
__device__ __forceinline__ void cpa16(uint32_t dst, const void* src) {
    asm volatile("cp.async.cg.shared.global [%0], [%1], 16;" :: "r"(dst), "l"(src));
}
#define CP_COMMIT() asm volatile("cp.async.commit_group;" ::: "memory")

__device__ __forceinline__ void ldm4(uint32_t* r, uint32_t a) {
    asm volatile("ldmatrix.sync.aligned.m8n8.x4.shared.b16 {%0,%1,%2,%3}, [%4];"
                 : "=r"(r[0]), "=r"(r[1]), "=r"(r[2]), "=r"(r[3]) : "r"(a));
}
__device__ __forceinline__ void ldm4t(uint32_t* r, uint32_t a) {
    asm volatile("ldmatrix.sync.aligned.m8n8.x4.trans.shared.b16 {%0,%1,%2,%3}, [%4];"
                 : "=r"(r[0]), "=r"(r[1]), "=r"(r[2]), "=r"(r[3]) : "r"(a));
}
__device__ __forceinline__ void mma16(float* d, const uint32_t* a, const uint32_t* b) {
    asm volatile(
        "mma.sync.aligned.m16n8k16.row.col.f32.f16.f16.f32 "
        "{%0,%1,%2,%3}, {%4,%5,%6,%7}, {%8,%9}, {%0,%1,%2,%3};"
        : "+f"(d[0]), "+f"(d[1]), "+f"(d[2]), "+f"(d[3])
        : "r"(a[0]), "r"(a[1]), "r"(a[2]), "r"(a[3]), "r"(b[0]), "r"(b[1]));
}
__device__ __forceinline__ void split2(float x, float y, uint32_t& h, uint32_t& l) {
    __half2 hh = __float22half2_rn(make_float2(x, y));
    float rx = x - __half2float(__low2half(hh));
    float ry = y - __half2float(__high2half(hh));
    __half2 ll = __float22half2_rn(make_float2(rx, ry));
    h = *reinterpret_cast<uint32_t*>(&hh);
    l = *reinterpret_cast<uint32_t*>(&ll);
}
__device__ __forceinline__ uint32_t pack_h2(float x, float y) {
    __half2 hh = __float22half2_rn(make_float2(x, y));
    return *reinterpret_cast<uint32_t*>(&hh);
}

// ---------------------------------------------------------------------------
// fp32 -> fp16 hi/lo split
// ---------------------------------------------------------------------------
__global__ void __launch_bounds__(256)
split_pair(const float2* __restrict__ in, __half2* __restrict__ oh,
           __half2* __restrict__ ol, int n2)
{
    int i = blockIdx.x * blockDim.x + threadIdx.x;
    if (i >= n2) return;
    float2 v = in[i];
    uint32_t h, l;
    split2(v.x, v.y, h, l);
    oh[i] = *reinterpret_cast<__half2*>(&h);
    ol[i] = *reinterpret_cast<__half2*>(&l);
}

// ---------------------------------------------------------------------------
// fp16-compensated GEMM v3 (NT): 128x128 tile, BK=32, 3-stage pipeline,
// one __syncthreads per chunk, 2 CTAs/SM. (Round-10, best known)
// ---------------------------------------------------------------------------
#define GSM 98304

template<int NOUT, bool SPLIT>
__global__ void __launch_bounds__(256, 2)
gemm16(const __half* __restrict__ Ah, const __half* __restrict__ Al,
       const __half* __restrict__ Bh, const __half* __restrict__ Bl,
       float* __restrict__ outF, __half* __restrict__ outH,
       __half* __restrict__ outL)
{
    extern __shared__ char smx[];
    const uint32_t smB = su32(smx);
    const int tid  = threadIdx.x;
    const int lane = tid & 31;
    const int wid  = tid >> 5;
    const int wm   = wid & 1;
    const int wn   = wid >> 1;
    const int lr   = lane & 7, g = lane >> 3;
    const int qr   = lane >> 2, qc = lane & 3;
    const int bm   = blockIdx.y * 128;
    const int bn   = blockIdx.x * 128;

    const int aCh = g >> 1;
    const int bCh = g & 1;
    const int aRowF = lr + ((g & 1) << 3);
    const int bRowF = lr + ((g >> 1) << 3);

    const int id0 = tid * 2, id1 = tid * 2 + 1;
    const int r0 = id0 >> 2, c0 = id0 & 3;
    const int r1 = id1 >> 2, c1 = id1 & 3;
    const uint32_t o0 = r0 * 64 + (((c0 ^ ((r0 >> 1) & 3))) << 4);
    const uint32_t o1 = r1 * 64 + (((c1 ^ ((r1 >> 1) & 3))) << 4);

    auto stage = [&](int k0, int s) {
        const uint32_t bb = smB + s * 32768;
        const size_t a0 = (size_t)(bm + r0) * 1024 + k0 + c0 * 8;
        const size_t a1 = (size_t)(bm + r1) * 1024 + k0 + c1 * 8;
        const size_t b0 = (size_t)(bn + r0) * 1024 + k0 + c0 * 8;
        const size_t b1 = (size_t)(bn + r1) * 1024 + k0 + c1 * 8;
        cpa16(bb + o0,         Ah + a0);  cpa16(bb + o1,         Ah + a1);
        cpa16(bb + 8192 + o0,  Al + a0);  cpa16(bb + 8192 + o1,  Al + a1);
        cpa16(bb + 16384 + o0, Bh + b0);  cpa16(bb + 16384 + o1, Bh + b1);
        cpa16(bb + 24576 + o0, Bl + b0);  cpa16(bb + 24576 + o1, Bl + b1);
        CP_COMMIT();
    };

    float c[4][4][4];
#pragma unroll
    for (int i = 0; i < 4; i++)
#pragma unroll
        for (int j = 0; j < 4; j++)
#pragma unroll
            for (int e = 0; e < 4; e++) c[i][j][e] = 0.f;

    stage(0, 0);
    stage(32, 1);

    for (int ki = 0; ki < 32; ki++) {
        if (ki < 31) asm volatile("cp.async.wait_group 1;" ::: "memory");
        else         asm volatile("cp.async.wait_group 0;" ::: "memory");
        __syncthreads();
        if (ki + 2 < 32) stage((ki + 2) * 32, (ki + 2) % 3);

        const uint32_t st = smB + (ki % 3) * 32768;

#pragma unroll
        for (int kk = 0; kk < 2; kk++) {
            uint32_t af[4][4];
#pragma unroll
            for (int i = 0; i < 4; i++) {
                const int row = wm * 64 + i * 16 + aRowF;
                ldm4(af[i], st + row * 64 +
                     (((2 * kk + aCh) ^ ((row >> 1) & 3)) << 4));
            }
            uint32_t bh4[2][4], bl4[2][4];
#pragma unroll
            for (int jp = 0; jp < 2; jp++) {
                const int row = wn * 32 + jp * 16 + bRowF;
                const uint32_t a = st + 16384 + row * 64 +
                                   (((2 * kk + bCh) ^ ((row >> 1) & 3)) << 4);
                ldm4(bh4[jp], a);
                ldm4(bl4[jp], a + 8192);
            }
#pragma unroll
            for (int jp = 0; jp < 2; jp++)
#pragma unroll
                for (int i = 0; i < 4; i++) {
                    mma16(c[i][2 * jp],     af[i], bh4[jp]);
                    mma16(c[i][2 * jp + 1], af[i], bh4[jp] + 2);
                }
#pragma unroll
            for (int jp = 0; jp < 2; jp++)
#pragma unroll
                for (int i = 0; i < 4; i++) {
                    mma16(c[i][2 * jp],     af[i], bl4[jp]);
                    mma16(c[i][2 * jp + 1], af[i], bl4[jp] + 2);
                }
#pragma unroll
            for (int i = 0; i < 4; i++) {
                const int row = wm * 64 + i * 16 + aRowF;
                ldm4(af[i], st + 8192 + row * 64 +
                     (((2 * kk + aCh) ^ ((row >> 1) & 3)) << 4));
            }
#pragma unroll
            for (int jp = 0; jp < 2; jp++)
#pragma unroll
                for (int i = 0; i < 4; i++) {
                    mma16(c[i][2 * jp],     af[i], bh4[jp]);
                    mma16(c[i][2 * jp + 1], af[i], bh4[jp] + 2);
                }
        }
    }

#pragma unroll
    for (int i = 0; i < 4; i++) {
#pragma unroll
        for (int j = 0; j < 4; j++) {
            const int row = bm + wm * 64 + i * 16 + qr;
            const int col = bn + wn * 32 + j * 8 + 2 * qc;
            if (SPLIT) {
                const float sc = (col < 1024) ? QSCALE : 1.f;
                uint32_t h0, l0, h1, l1;
                split2(c[i][j][0] * sc, c[i][j][1] * sc, h0, l0);
                split2(c[i][j][2] * sc, c[i][j][3] * sc, h1, l1);
                *(uint32_t*)(outH + (size_t)row * NOUT + col) = h0;
                *(uint32_t*)(outL + (size_t)row * NOUT + col) = l0;
                *(uint32_t*)(outH + (size_t)(row + 8) * NOUT + col) = h1;
                *(uint32_t*)(outL + (size_t)(row + 8) * NOUT + col) = l1;
            } else {
                *(float2*)(outF + (size_t)row * NOUT + col) =
                    make_float2(c[i][j][0], c[i][j][1]);
                *(float2*)(outF + (size_t)(row + 8) * NOUT + col) =
                    make_float2(c[i][j][2], c[i][j][3]);
            }
        }
    }
}

// ---------------------------------------------------------------------------
// Flash attention (causal), v3: S fully compensated; PV single-pass Ph*Vh
// (error ~2e-4 RMS, within budget). exp2-domain softmax (Q pre-scaled by
// 0.125*log2e). Stage = Kh|Kl|Vh (24KB); 2 stages = 48KB smem, 3 CTAs/SM.
// ---------------------------------------------------------------------------
#define FA_SMEM 49152

__global__ void __launch_bounds__(128, 3)
flash16(const __half* __restrict__ qh, const __half* __restrict__ ql,
        float* __restrict__ out)
{
    extern __shared__ char smx[];
    const uint32_t smB = su32(smx);
    const int tid  = threadIdx.x;
    const int w    = tid >> 5;
    const int lane = tid & 31;
    const int lr   = lane & 7, g = lane >> 3;
    const int qr   = lane >> 2, qc = lane & 3;
    const int bhx  = blockIdx.y;
    const int b    = bhx >> 4;
    const int hh   = bhx & 15;
    const int m0   = blockIdx.x * 64;

    const size_t base = (size_t)b * T_ * 3072 + hh * 64;
    const __half* qhp = qh + base;
    const __half* qlp = ql + base;
    const __half* khp = qhp + 1024;
    const __half* klp = qlp + 1024;
    const __half* vhp = qhp + 2048;

    int sRow[4], sC[4];
    uint32_t sDst[4];
#pragma unroll
    for (int q = 0; q < 4; q++) {
        int id = tid * 4 + q;
        sRow[q] = id >> 3;
        sC[q]   = id & 7;
        sDst[q] = sRow[q] * 128 + ((sC[q] ^ (sRow[q] & 7)) << 4);
    }

    // stage s at smB + s*24576: Kh | Kl | Vh (8KB each)
    auto stage_kv = [&](int j0, int s) {
        const uint32_t bb = smB + s * 24576;
#pragma unroll
        for (int q = 0; q < 4; q++) {
            const size_t so = (size_t)(j0 + sRow[q]) * 3072 + sC[q] * 8;
            cpa16(bb + sDst[q],         khp + so);
            cpa16(bb + 8192  + sDst[q], klp + so);
            cpa16(bb + 16384 + sDst[q], vhp + so);
        }
        CP_COMMIT();
    };

    // stage Q into first 16KB (recycled as stage 0 afterwards)
#pragma unroll
    for (int q = 0; q < 4; q++) {
        const size_t so = (size_t)(m0 + sRow[q]) * 3072 + sC[q] * 8;
        cpa16(smB + sDst[q],        qhp + so);
        cpa16(smB + 8192 + sDst[q], qlp + so);
    }
    CP_COMMIT();
    asm volatile("cp.async.wait_group 0;" ::: "memory");
    __syncthreads();

    const int aRow = lr + ((g & 1) << 3), aCh = g >> 1;
    const int kRow = lr + ((g >> 1) << 3), kCh = g & 1;
    uint32_t qfh[4][4], qfl[4][4];
#pragma unroll
    for (int kk = 0; kk < 4; kk++) {
        uint32_t a = smB + (w * 16 + aRow) * 128 + (((2 * kk + aCh) ^ lr) << 4);
        ldm4(qfh[kk], a);
        ldm4(qfl[kk], a + 8192);
    }
    __syncthreads();          // Q fragments in regs before stage-0 overwrite
    stage_kv(0, 0);

    float o_[8][4];
#pragma unroll
    for (int n = 0; n < 8; n++)
#pragma unroll
        for (int e = 0; e < 4; e++) o_[n][e] = 0.f;
    float m0v = -1e30f, m1v = -1e30f, l0v = 0.f, l1v = 0.f;
    const int row0 = m0 + w * 16 + qr;

    for (int j0 = 0; j0 <= m0; j0 += 64) {
        const int st = (j0 >> 6) & 1;
        if (j0 + 64 <= m0) {
            stage_kv(j0 + 64, st ^ 1);
            asm volatile("cp.async.wait_group 1;" ::: "memory");
        } else {
            asm volatile("cp.async.wait_group 0;" ::: "memory");
        }
        __syncthreads();
        const uint32_t KB = smB + st * 24576;
        const uint32_t VB = KB + 16384;

        float s_[8][4];
#pragma unroll
        for (int n = 0; n < 8; n++)
#pragma unroll
            for (int e = 0; e < 4; e++) s_[n][e] = 0.f;

        // ---- S = Q K^T (3-pass compensated) ----
#pragma unroll
        for (int kk = 0; kk < 4; kk++) {
            uint32_t kh4[4][4], kl4[4][4];
#pragma unroll
            for (int np = 0; np < 4; np++) {
                uint32_t a = KB + np * 2048 + kRow * 128 +
                             (((2 * kk + kCh) ^ lr) << 4);
                ldm4(kh4[np], a);
                ldm4(kl4[np], a + 8192);
            }
#pragma unroll
            for (int np = 0; np < 4; np++) {
                mma16(s_[2 * np],     qfh[kk], kh4[np]);
                mma16(s_[2 * np + 1], qfh[kk], kh4[np] + 2);
            }
#pragma unroll
            for (int np = 0; np < 4; np++) {
                mma16(s_[2 * np],     qfh[kk], kl4[np]);
                mma16(s_[2 * np + 1], qfh[kk], kl4[np] + 2);
            }
#pragma unroll
            for (int np = 0; np < 4; np++) {
                mma16(s_[2 * np],     qfl[kk], kh4[np]);
                mma16(s_[2 * np + 1], qfl[kk], kh4[np] + 2);
            }
        }

        if (j0 == m0) {
#pragma unroll
            for (int n = 0; n < 8; n++) {
                const int key = j0 + n * 8 + 2 * qc;
                if (key     > row0)     s_[n][0] = -1e30f;
                if (key + 1 > row0)     s_[n][1] = -1e30f;
                if (key     > row0 + 8) s_[n][2] = -1e30f;
                if (key + 1 > row0 + 8) s_[n][3] = -1e30f;
            }
        }

        // ---- online softmax in exp2 domain ----
        float mx0 = -1e30f, mx1 = -1e30f;
#pragma unroll
        for (int n = 0; n < 8; n++) {
            mx0 = fmaxf(mx0, fmaxf(s_[n][0], s_[n][1]));
            mx1 = fmaxf(mx1, fmaxf(s_[n][2], s_[n][3]));
        }
        mx0 = fmaxf(mx0, __shfl_xor_sync(0xffffffffu, mx0, 1));
        mx0 = fmaxf(mx0, __shfl_xor_sync(0xffffffffu, mx0, 2));
        mx1 = fmaxf(mx1, __shfl_xor_sync(0xffffffffu, mx1, 1));
        mx1 = fmaxf(mx1, __shfl_xor_sync(0xffffffffu, mx1, 2));
        const float mn0 = fmaxf(m0v, mx0);
        const float mn1 = fmaxf(m1v, mx1);
        const float c0 = exp2f(m0v - mn0);
        const float c1 = exp2f(m1v - mn1);
        m0v = mn0; m1v = mn1;
        l0v *= c0;  l1v *= c1;
#pragma unroll
        for (int n = 0; n < 8; n++) {
            o_[n][0] *= c0; o_[n][1] *= c0;
            o_[n][2] *= c1; o_[n][3] *= c1;
        }

        uint32_t pA[8], pB[8];
        float ps0 = 0.f, ps1 = 0.f;
#pragma unroll
        for (int n = 0; n < 8; n++) {
            float p0 = exp2f(s_[n][0] - mn0);
            float p1 = exp2f(s_[n][1] - mn0);
            float p2 = exp2f(s_[n][2] - mn1);
            float p3 = exp2f(s_[n][3] - mn1);
            ps0 += p0 + p1;
            ps1 += p2 + p3;
            pA[n] = pack_h2(p0, p1);
            pB[n] = pack_h2(p2, p3);
        }
        ps0 += __shfl_xor_sync(0xffffffffu, ps0, 1);
        ps0 += __shfl_xor_sync(0xffffffffu, ps0, 2);
        ps1 += __shfl_xor_sync(0xffffffffu, ps1, 1);
        ps1 += __shfl_xor_sync(0xffffffffu, ps1, 2);
        l0v += ps0; l1v += ps1;

        // ---- O += Ph * Vh (single pass) ----
#pragma unroll
        for (int kk = 0; kk < 4; kk++) {
            uint32_t ah4[4] = { pA[2 * kk], pB[2 * kk],
                                pA[2 * kk + 1], pB[2 * kk + 1] };
#pragma unroll
            for (int np = 0; np < 4; np++) {
                uint32_t vh4[4];
                uint32_t a = VB + kk * 2048 + aRow * 128 +
                             (((2 * np + aCh) ^ lr) << 4);
                ldm4t(vh4, a);
                mma16(o_[2 * np],     ah4, vh4);
                mma16(o_[2 * np + 1], ah4, vh4 + 2);
            }
        }
        __syncthreads();
    }

    const float i0 = 1.f / l0v;
    const float i1 = 1.f / l1v;
    float* oP0 = out + ((size_t)b * T_ + row0) * C_ + hh * 64;
    float* oP1 = oP0 + 8 * C_;
#pragma unroll
    for (int n = 0; n < 8; n++) {
        *(float2*)(oP0 + n * 8 + 2 * qc) = make_float2(o_[n][0] * i0, o_[n][1] * i0);
        *(float2*)(oP1 + n * 8 + 2 * qc) = make_float2(o_[n][2] * i1, o_[n][3] * i1);
    }
}

// ---------------------------------------------------------------------------
// Depthwise causal conv (K=4) + bias + residual -> fp16 hi/lo
// ---------------------------------------------------------------------------
__global__ void __launch_bounds__(256)
conv_split(const float* __restrict__ x, const float* __restrict__ w,
           const float* __restrict__ bias, __half* __restrict__ yh,
           __half* __restrict__ yl)
{
    int i2 = blockIdx.x * blockDim.x + threadIdx.x;
    if (i2 >= MTOK * C_ / 2) return;
    const int idx = i2 * 2;
    const int c = idx & (C_ - 1);
    const int t = (idx >> 10) & (T_ - 1);

    float s0 = bias[c]     + x[idx];
    float s1 = bias[c + 1] + x[idx + 1];
#pragma unroll
    for (int k = 0; k < 4; k++) {
        int ts = t + k - 3;
        if (ts >= 0) {
            s0 += w[c * 4 + k]       * x[idx + (k - 3) * C_];
            s1 += w[(c + 1) * 4 + k] * x[idx + 1 + (k - 3) * C_];
        }
    }
    uint32_t h, l;
    split2(s0, s1, h, l);
    *(uint32_t*)(yh + idx) = h;
    *(uint32_t*)(yl + idx) = l;
}

// ---------------------------------------------------------------------------
// Launch
// ---------------------------------------------------------------------------
extern "C" void kernel_launch(void* const* d_in, const int* in_sizes, int n_in,
                              void* d_out, int out_size)
{
    const float* x     = (const float*)d_in[0];
    const float* Wqkv  = (const float*)d_in[1];
    const float* Wout  = (const float*)d_in[2];
    const float* convw = (const float*)d_in[3];
    const float* convb = (const float*)d_in[4];
    float* out = (float*)d_out;

    __half *xh, *xl, *wqh, *wql, *woh, *wol, *qh, *ql, *ch, *cl;
    float* attn;
    cudaGetSymbolAddress((void**)&xh,  g_xh);
    cudaGetSymbolAddress((void**)&xl,  g_xl);
    cudaGetSymbolAddress((void**)&wqh, g_wqh);
    cudaGetSymbolAddress((void**)&wql, g_wql);
    cudaGetSymbolAddress((void**)&woh, g_woh);
    cudaGetSymbolAddress((void**)&wol, g_wol);
    cudaGetSymbolAddress((void**)&qh,  g_qh);
    cudaGetSymbolAddress((void**)&ql,  g_ql);
    cudaGetSymbolAddress((void**)&ch,  g_ch);
    cudaGetSymbolAddress((void**)&cl,  g_cl);
    cudaGetSymbolAddress((void**)&attn, g_attn);

    cudaFuncSetAttribute(gemm16<3072, true>,
                         cudaFuncAttributeMaxDynamicSharedMemorySize, GSM);
    cudaFuncSetAttribute(gemm16<1024, false>,
                         cudaFuncAttributeMaxDynamicSharedMemorySize, GSM);
    cudaFuncSetAttribute(flash16,
                         cudaFuncAttributeMaxDynamicSharedMemorySize, FA_SMEM);

    // 0) split inputs
    split_pair<<<MTOK * C_ / 2 / 256, 256>>>((const float2*)x,
                                             (__half2*)xh, (__half2*)xl,
                                             MTOK * C_ / 2);
    split_pair<<<3 * C_ * C_ / 2 / 256, 256>>>((const float2*)Wqkv,
                                               (__half2*)wqh, (__half2*)wql,
                                               3 * C_ * C_ / 2);
    split_pair<<<C_ * C_ / 2 / 256, 256>>>((const float2*)Wout,
                                           (__half2*)woh, (__half2*)wol,
                                           C_ * C_ / 2);

    // 1) QKV projection (split hi/lo out, Q pre-scaled by 0.125*log2e)
    gemm16<3072, true><<<dim3(24, 64), 256, GSM>>>(xh, xl, wqh, wql,
                                                   nullptr, qh, ql);

    // 2) attention (exp2-domain softmax, single-pass PV)
    flash16<<<dim3(T_ / 64, B_ * H_), 128, FA_SMEM>>>(qh, ql, attn);

    // 3) conv + residual -> split
    conv_split<<<MTOK * C_ / 2 / 256, 256>>>(attn, convw, convb, ch, cl);

    // 4) output projection
    gemm16<1024, false><<<dim3(8, 64), 256, GSM>>>(ch, cl, woh, wol,
                                                   out, nullptr, nullptr);
}